// round 12
// baseline (speedup 1.0000x reference)
#include <cuda_runtime.h>
#include <cuda_bf16.h>
#include <math.h>
#include <stdint.h>

#define N_NODES 50000
#define N_EDGES 800000
#define W_TOTAL 94208  // sum of K*Dout over 6 layers

// ---------------- static device scratch (allocation-free rule) ----------------
__device__ float g_bufA[N_NODES * 256];
__device__ float g_bufB[N_NODES * 256];
__device__ int   g_rowbeg[N_NODES];
__device__ int   g_rowend[N_NODES];
__device__ int   g_cursor[N_NODES];
__device__ int   g_cnt[N_NODES];
__device__ float g_dinv[N_NODES];
__device__ int   g_col[N_EDGES];
__device__ int   g_total;
__device__ unsigned short g_whi[W_TOTAL];  // bf16 hi, transposed [Dout][K]
__device__ unsigned short g_wlo[W_TOTAL];  // bf16 lo

// ---------------- CSR build (scan-free) ----------------
__global__ void hist_kernel(const int* __restrict__ ei) {
    int e = blockIdx.x * blockDim.x + threadIdx.x;
    if (e < N_EDGES) atomicAdd(&g_cnt[ei[N_EDGES + e]], 1);
}

__global__ void alloc_kernel() {
    int i = blockIdx.x * blockDim.x + threadIdx.x;
    if (i < N_NODES) {
        int c = g_cnt[i];
        g_dinv[i] = rsqrtf((float)c + 1.0f);
        int beg = atomicAdd(&g_total, c);
        g_rowbeg[i] = beg;
        g_rowend[i] = beg + c;
        g_cursor[i] = beg;
    }
}

__global__ void scatter_kernel(const int* __restrict__ ei) {
    int e = blockIdx.x * blockDim.x + threadIdx.x;
    if (e < N_EDGES) {
        int s = ei[e];
        int d = ei[N_EDGES + e];
        int pos = atomicAdd(&g_cursor[d], 1);
        g_col[pos] = s;
    }
}

// ---------------- W prep (ALL layers in ONE launch) ----------------
// fp32 [K][Dout] -> bf16 hi/lo transposed [Dout][K], flat index over W_TOTAL
__global__ void wprep_all_kernel(
    const float* __restrict__ W1, const float* __restrict__ W2,
    const float* __restrict__ W3, const float* __restrict__ W4,
    const float* __restrict__ W5, const float* __restrict__ W6) {
    int i = blockIdx.x * blockDim.x + threadIdx.x;
    if (i >= W_TOTAL) return;
    const float* W; int off, K, Dout;
    if      (i < 8192)  { W = W1; off = 0;     K = 128; Dout = 64;  }
    else if (i < 16384) { W = W2; off = 8192;  K = 64;  Dout = 128; }
    else if (i < 49152) { W = W3; off = 16384; K = 128; Dout = 256; }
    else if (i < 81920) { W = W4; off = 49152; K = 256; Dout = 128; }
    else if (i < 90112) { W = W5; off = 81920; K = 128; Dout = 64;  }
    else                { W = W6; off = 90112; K = 64;  Dout = 64;  }
    int local = i - off;
    int k = local / Dout, n = local % Dout;
    float v = W[local];
    __nv_bfloat16 h = __float2bfloat16(v);
    float r = v - __bfloat162float(h);
    g_whi[off + n * K + k] = __bfloat16_as_ushort(h);
    g_wlo[off + n * K + k] = __bfloat16_as_ushort(__float2bfloat16(r));
}

// ---------------- warp MMA: m16n8k16 bf16 -> fp32 (sm_80+ PTX) ----------
__device__ __forceinline__ void mma16816(float* d, const uint32_t* a, const uint32_t* b) {
    asm volatile(
        "mma.sync.aligned.m16n8k16.row.col.f32.bf16.bf16.f32 "
        "{%0,%1,%2,%3}, {%4,%5,%6,%7}, {%8,%9}, {%0,%1,%2,%3};"
        : "+f"(d[0]), "+f"(d[1]), "+f"(d[2]), "+f"(d[3])
        : "r"(a[0]), "r"(a[1]), "r"(a[2]), "r"(a[3]), "r"(b[0]), "r"(b[1]));
}

// ---------------- tensor-core GEMM: C = A[NxK] @ W[KxDout] (bf16-split, 3 MMAs) ----------
// BM=128, BN template (64 or 128), BK=32. 8 warps: warpRow 0..3 (32 rows),
// warpCol 0..1 (BN/2 cols, NF=BN/16 n-frags). k-permuted contiguous fragment loads.
template <int BN, int ACT, int SCALE>  // ACT: 0 none, 1 relu; SCALE: mult by dinv[row]
__global__ void __launch_bounds__(256) mma_gemm_kernel(
    const float* __restrict__ A,
    const unsigned short* __restrict__ whi, const unsigned short* __restrict__ wlo,
    const float* __restrict__ bias, float* __restrict__ C,
    int K, int Dout) {
    constexpr int BK = 32;
    constexpr int SA = 40;   // row stride in halves (80B)
    constexpr int NF = BN / 16;
    __shared__ __align__(16) unsigned short Ah[128 * SA];
    __shared__ __align__(16) unsigned short Al[128 * SA];
    __shared__ __align__(16) unsigned short Bh[BN * SA];
    __shared__ __align__(16) unsigned short Bl[BN * SA];

    const int t = threadIdx.x;
    const int lane = t & 31, wid = t >> 5;
    const int g = lane >> 2, tc = lane & 3;
    const int warpRow = wid & 3, warpCol = wid >> 2;
    const int rowBase = blockIdx.x * 128;
    const int colBase = blockIdx.y * BN;

    float d[2][NF][4] = {};

    for (int kb = 0; kb < K; kb += BK) {
        // ---- stage A tile [128][BK] with fused fp32 -> bf16 hi/lo split ----
        for (int task = t; task < 128 * (BK / 8); task += 256) {
            int row = task >> 2;             // BK/8 == 4
            int col0 = (task & 3) * 8;
            float v[8];
            int grow = rowBase + row;
            if (grow < N_NODES) {
                const float* p = A + (size_t)grow * K + kb + col0;
                float4 x0 = *reinterpret_cast<const float4*>(p);
                float4 x1 = *reinterpret_cast<const float4*>(p + 4);
                v[0]=x0.x; v[1]=x0.y; v[2]=x0.z; v[3]=x0.w;
                v[4]=x1.x; v[5]=x1.y; v[6]=x1.z; v[7]=x1.w;
            } else {
                #pragma unroll
                for (int j = 0; j < 8; j++) v[j] = 0.f;
            }
            unsigned int hp[4], lp[4];
            #pragma unroll
            for (int j = 0; j < 4; j++) {
                __nv_bfloat16 h0 = __float2bfloat16(v[2*j]);
                __nv_bfloat16 h1 = __float2bfloat16(v[2*j+1]);
                float r0 = v[2*j]   - __bfloat162float(h0);
                float r1 = v[2*j+1] - __bfloat162float(h1);
                hp[j] = (unsigned int)__bfloat16_as_ushort(h0)
                      | ((unsigned int)__bfloat16_as_ushort(h1) << 16);
                lp[j] = (unsigned int)__bfloat16_as_ushort(__float2bfloat16(r0))
                      | ((unsigned int)__bfloat16_as_ushort(__float2bfloat16(r1)) << 16);
            }
            *reinterpret_cast<uint4*>(&Ah[row * SA + col0]) = make_uint4(hp[0],hp[1],hp[2],hp[3]);
            *reinterpret_cast<uint4*>(&Al[row * SA + col0]) = make_uint4(lp[0],lp[1],lp[2],lp[3]);
        }
        // ---- stage B tile [BN][BK] from pre-split W^T ([Dout][K] bf16) ----
        for (int task = t; task < BN * (BK / 8); task += 256) {
            int n = task >> 2;
            int col0 = (task & 3) * 8;
            size_t src = (size_t)(colBase + n) * K + kb + col0;
            *reinterpret_cast<uint4*>(&Bh[n * SA + col0]) =
                *reinterpret_cast<const uint4*>(whi + src);
            *reinterpret_cast<uint4*>(&Bl[n * SA + col0]) =
                *reinterpret_cast<const uint4*>(wlo + src);
        }
        __syncthreads();

        #pragma unroll
        for (int ks = 0; ks < 2; ks++) {
            const int kk = ks * 16;
            uint32_t ahf[2][4], alf[2][4];
            #pragma unroll
            for (int i = 0; i < 2; i++) {
                int r0 = warpRow * 32 + i * 16 + g;
                uint2 x = *reinterpret_cast<const uint2*>(&Ah[r0 * SA + kk + tc * 4]);
                uint2 y = *reinterpret_cast<const uint2*>(&Ah[(r0 + 8) * SA + kk + tc * 4]);
                ahf[i][0] = x.x; ahf[i][2] = x.y; ahf[i][1] = y.x; ahf[i][3] = y.y;
                uint2 xl = *reinterpret_cast<const uint2*>(&Al[r0 * SA + kk + tc * 4]);
                uint2 yl = *reinterpret_cast<const uint2*>(&Al[(r0 + 8) * SA + kk + tc * 4]);
                alf[i][0] = xl.x; alf[i][2] = xl.y; alf[i][1] = yl.x; alf[i][3] = yl.y;
            }
            #pragma unroll
            for (int j = 0; j < NF; j++) {
                int n = warpCol * (BN / 2) + j * 8 + g;
                uint32_t bhf[2], blf[2];
                uint2 x = *reinterpret_cast<const uint2*>(&Bh[n * SA + kk + tc * 4]);
                bhf[0] = x.x; bhf[1] = x.y;
                uint2 y = *reinterpret_cast<const uint2*>(&Bl[n * SA + kk + tc * 4]);
                blf[0] = y.x; blf[1] = y.y;
                #pragma unroll
                for (int i = 0; i < 2; i++) {
                    mma16816(d[i][j], ahf[i], bhf);
                    mma16816(d[i][j], alf[i], bhf);
                    mma16816(d[i][j], ahf[i], blf);
                }
            }
        }
        __syncthreads();
    }

    // ---- epilogue: d frag (i,j): rows r0,r0+8; cols col,col+1 ----
    #pragma unroll
    for (int i = 0; i < 2; i++) {
        int r0 = rowBase + warpRow * 32 + i * 16 + g;
        int r1 = r0 + 8;
        float s0 = 1.0f, s1 = 1.0f;
        if (SCALE) {
            if (r0 < N_NODES) s0 = g_dinv[r0];
            if (r1 < N_NODES) s1 = g_dinv[r1];
        }
        #pragma unroll
        for (int j = 0; j < NF; j++) {
            int col = colBase + warpCol * (BN / 2) + j * 8 + tc * 2;
            float b0 = 0.f, b1 = 0.f;
            if (bias) { b0 = bias[col]; b1 = bias[col + 1]; }
            float v0 = d[i][j][0] + b0, v1 = d[i][j][1] + b1;
            float v2 = d[i][j][2] + b0, v3 = d[i][j][3] + b1;
            if (ACT == 1) {
                v0 = fmaxf(v0, 0.f); v1 = fmaxf(v1, 0.f);
                v2 = fmaxf(v2, 0.f); v3 = fmaxf(v3, 0.f);
            }
            if (r0 < N_NODES)
                *reinterpret_cast<float2*>(&C[(size_t)r0 * Dout + col]) =
                    make_float2(v0 * s0, v1 * s0);
            if (r1 < N_NODES)
                *reinterpret_cast<float2*>(&C[(size_t)r1 * Dout + col]) =
                    make_float2(v2 * s1, v3 * s1);
        }
    }
}

// ---------------- Aggregation (separable norm) ----------------
template <int ACT, int PRESCALE>  // ACT: 0 none, 1 relu, 2 sigmoid
__global__ void __launch_bounds__(256) agg64_kernel(
    const float* __restrict__ in, float* __restrict__ out,
    const float* __restrict__ bias) {
    int warp = (blockIdx.x * blockDim.x + threadIdx.x) >> 5;
    if (warp >= N_NODES) return;
    int lane = threadIdx.x & 31;
    const int off = lane * 2;

    float2 self = *reinterpret_cast<const float2*>(in + (size_t)warp * 64 + off);
    float ax = self.x, ay = self.y;

    int e = g_rowbeg[warp], end = g_rowend[warp];
    for (; e + 4 <= end; e += 4) {
        int s0 = g_col[e], s1 = g_col[e+1], s2 = g_col[e+2], s3 = g_col[e+3];
        float2 p0 = *reinterpret_cast<const float2*>(in + (size_t)s0 * 64 + off);
        float2 p1 = *reinterpret_cast<const float2*>(in + (size_t)s1 * 64 + off);
        float2 p2 = *reinterpret_cast<const float2*>(in + (size_t)s2 * 64 + off);
        float2 p3 = *reinterpret_cast<const float2*>(in + (size_t)s3 * 64 + off);
        ax += p0.x; ay += p0.y;
        ax += p1.x; ay += p1.y;
        ax += p2.x; ay += p2.y;
        ax += p3.x; ay += p3.y;
    }
    for (; e < end; e++) {
        int si = g_col[e];
        float2 p = *reinterpret_cast<const float2*>(in + (size_t)si * 64 + off);
        ax += p.x; ay += p.y;
    }

    float dd = g_dinv[warp];
    ax *= dd; ay *= dd;
    if (bias) {
        const float2 b = *reinterpret_cast<const float2*>(bias + off);
        ax += b.x; ay += b.y;
    }
    if (ACT == 1) { ax = fmaxf(ax, 0.f); ay = fmaxf(ay, 0.f); }
    if (ACT == 2) {
        ax = 1.0f / (1.0f + expf(-ax));
        ay = 1.0f / (1.0f + expf(-ay));
    }
    if (PRESCALE) { ax *= dd; ay *= dd; }
    *reinterpret_cast<float2*>(out + (size_t)warp * 64 + off) = make_float2(ax, ay);
}

template <int ACT, int PRESCALE>
__global__ void __launch_bounds__(256) agg128_kernel(
    const float* __restrict__ in, float* __restrict__ out,
    const float* __restrict__ bias) {
    int warp = (blockIdx.x * blockDim.x + threadIdx.x) >> 5;
    if (warp >= N_NODES) return;
    int lane = threadIdx.x & 31;
    const int off = lane * 4;

    float4 self = *reinterpret_cast<const float4*>(in + (size_t)warp * 128 + off);
    float ax = self.x, ay = self.y, az = self.z, aw = self.w;

    int e = g_rowbeg[warp], end = g_rowend[warp];
    for (; e + 4 <= end; e += 4) {
        int s0 = g_col[e], s1 = g_col[e+1], s2 = g_col[e+2], s3 = g_col[e+3];
        float4 p0 = *reinterpret_cast<const float4*>(in + (size_t)s0 * 128 + off);
        float4 p1 = *reinterpret_cast<const float4*>(in + (size_t)s1 * 128 + off);
        float4 p2 = *reinterpret_cast<const float4*>(in + (size_t)s2 * 128 + off);
        float4 p3 = *reinterpret_cast<const float4*>(in + (size_t)s3 * 128 + off);
        ax += p0.x; ay += p0.y; az += p0.z; aw += p0.w;
        ax += p1.x; ay += p1.y; az += p1.z; aw += p1.w;
        ax += p2.x; ay += p2.y; az += p2.z; aw += p2.w;
        ax += p3.x; ay += p3.y; az += p3.z; aw += p3.w;
    }
    for (; e < end; e++) {
        int si = g_col[e];
        float4 p = *reinterpret_cast<const float4*>(in + (size_t)si * 128 + off);
        ax += p.x; ay += p.y; az += p.z; aw += p.w;
    }

    float dd = g_dinv[warp];
    ax *= dd; ay *= dd; az *= dd; aw *= dd;
    if (bias) {
        const float4 b = *reinterpret_cast<const float4*>(bias + off);
        ax += b.x; ay += b.y; az += b.z; aw += b.w;
    }
    if (ACT == 1) {
        ax = fmaxf(ax, 0.f); ay = fmaxf(ay, 0.f);
        az = fmaxf(az, 0.f); aw = fmaxf(aw, 0.f);
    }
    if (ACT == 2) {
        ax = 1.0f/(1.0f+expf(-ax)); ay = 1.0f/(1.0f+expf(-ay));
        az = 1.0f/(1.0f+expf(-az)); aw = 1.0f/(1.0f+expf(-aw));
    }
    if (PRESCALE) { ax *= dd; ay *= dd; az *= dd; aw *= dd; }
    *reinterpret_cast<float4*>(out + (size_t)warp * 128 + off) = make_float4(ax, ay, az, aw);
}

// ---------------- launch ----------------
extern "C" void kernel_launch(void* const* d_in, const int* in_sizes, int n_in,
                              void* d_out, int out_size) {
    const float* x  = (const float*)d_in[0];
    const int*   ei = (const int*)d_in[1];   // int32! (JAX x64 disabled)
    const float* W1 = (const float*)d_in[2],  *b1 = (const float*)d_in[3];
    const float* W2 = (const float*)d_in[4],  *b2 = (const float*)d_in[5];
    const float* W3 = (const float*)d_in[6],  *b3 = (const float*)d_in[7];
    const float* W4 = (const float*)d_in[8],  *b4 = (const float*)d_in[9];
    const float* W5 = (const float*)d_in[10], *b5 = (const float*)d_in[11];
    const float* W6 = (const float*)d_in[12], *b6 = (const float*)d_in[13];
    float* out = (float*)d_out;

    float *bufA, *bufB;
    cudaGetSymbolAddress((void**)&bufA, g_bufA);
    cudaGetSymbolAddress((void**)&bufB, g_bufB);
    void *cntPtr, *totPtr;
    cudaGetSymbolAddress(&cntPtr, g_cnt);
    cudaGetSymbolAddress(&totPtr, g_total);
    unsigned short *whi, *wlo;
    cudaGetSymbolAddress((void**)&whi, g_whi);
    cudaGetSymbolAddress((void**)&wlo, g_wlo);

    const int TB = 256;
    const int nodeBlocks = (N_NODES + TB - 1) / TB;
    const int edgeBlocks = (N_EDGES + TB - 1) / TB;
    const int aggBlocks  = (N_NODES * 32 + TB - 1) / TB;
    const int gemmRows   = (N_NODES + 127) / 128;

    // W layer offsets within g_whi/g_wlo
    const int wo1 = 0, wo2 = 8192, wo3 = 16384, wo4 = 49152, wo5 = 81920, wo6 = 90112;

    // ---- preprocessing: CSR + W split/transpose (single launch) ----
    cudaMemsetAsync(cntPtr, 0, N_NODES * sizeof(int));
    cudaMemsetAsync(totPtr, 0, sizeof(int));
    hist_kernel<<<edgeBlocks, TB>>>(ei);
    alloc_kernel<<<nodeBlocks, TB>>>();
    scatter_kernel<<<edgeBlocks, TB>>>(ei);
    wprep_all_kernel<<<(W_TOTAL + TB - 1) / TB, TB>>>(W1, W2, W3, W4, W5, W6);

    // L1: hs = dinv .* (x@W1); agg: dinv.*relu(dinv*sum + b1)  [prescaled for L2]
    mma_gemm_kernel<64,0,1><<<dim3(gemmRows, 1), TB>>>(x, whi + wo1, wlo + wo1, nullptr, bufA, 128, 64);
    agg64_kernel<1,1><<<aggBlocks, TB>>>(bufA, bufB, b1);

    // L2: agg -> GEMM bias+relu+scale (prescaled for L3 agg)   BN=128, single y-pass
    agg64_kernel<0,0><<<aggBlocks, TB>>>(bufB, bufA, nullptr);
    mma_gemm_kernel<128,1,1><<<dim3(gemmRows, 1), TB>>>(bufA, whi + wo2, wlo + wo2, b2, bufB, 64, 128);

    // L3: agg -> GEMM bias+relu (no scale; L4 is GEMM-first)   BN=128, 2 y-passes
    agg128_kernel<0,0><<<aggBlocks, TB>>>(bufB, bufA, nullptr);
    mma_gemm_kernel<128,1,0><<<dim3(gemmRows, 2), TB>>>(bufA, whi + wo3, wlo + wo3, b3, bufB, 128, 256);

    // L4: GEMM scale -> agg relu+b4                            BN=128, single y-pass
    mma_gemm_kernel<128,0,1><<<dim3(gemmRows, 1), TB>>>(bufB, whi + wo4, wlo + wo4, nullptr, bufA, 256, 128);
    agg128_kernel<1,0><<<aggBlocks, TB>>>(bufA, bufB, b4);

    // L5: GEMM scale -> agg relu+b5
    mma_gemm_kernel<64,0,1><<<dim3(gemmRows, 1), TB>>>(bufB, whi + wo5, wlo + wo5, nullptr, bufA, 128, 64);
    agg64_kernel<1,0><<<aggBlocks, TB>>>(bufA, bufB, b5);

    // L6: GEMM scale -> agg sigmoid+b6 -> d_out
    mma_gemm_kernel<64,0,1><<<dim3(gemmRows, 1), TB>>>(bufB, whi + wo6, wlo + wo6, nullptr, bufA, 64, 64);
    agg64_kernel<2,0><<<aggBlocks, TB>>>(bufA, out, b6);
}

// round 13
// speedup vs baseline: 1.0298x; 1.0298x over previous
#include <cuda_runtime.h>
#include <cuda_bf16.h>
#include <cuda_fp16.h>
#include <math.h>
#include <stdint.h>

#define N_NODES 50000
#define N_EDGES 800000
#define W_TOTAL 94208  // sum of K*Dout over 6 layers

// ---------------- static device scratch (allocation-free rule) ----------------
__device__ float g_bufA[N_NODES * 256];
__device__ float g_bufB[N_NODES * 256];
__device__ int   g_rowbeg[N_NODES];
__device__ int   g_rowend[N_NODES];
__device__ int   g_cursor[N_NODES];
__device__ int   g_cnt[N_NODES];
__device__ float g_dinv[N_NODES];
__device__ int   g_col[N_EDGES];
__device__ int   g_total;
__device__ unsigned short g_whi[W_TOTAL];  // bf16 hi, transposed [Dout][K]
__device__ unsigned short g_wlo[W_TOTAL];  // bf16 lo

// ---------------- CSR build (scan-free) ----------------
__global__ void hist_kernel(const int* __restrict__ ei) {
    int e = blockIdx.x * blockDim.x + threadIdx.x;
    if (e < N_EDGES) atomicAdd(&g_cnt[ei[N_EDGES + e]], 1);
}

__global__ void alloc_kernel() {
    int i = blockIdx.x * blockDim.x + threadIdx.x;
    if (i < N_NODES) {
        int c = g_cnt[i];
        g_dinv[i] = rsqrtf((float)c + 1.0f);
        int beg = atomicAdd(&g_total, c);
        g_rowbeg[i] = beg;
        g_rowend[i] = beg + c;
        g_cursor[i] = beg;
    }
}

__global__ void scatter_kernel(const int* __restrict__ ei) {
    int e = blockIdx.x * blockDim.x + threadIdx.x;
    if (e < N_EDGES) {
        int s = ei[e];
        int d = ei[N_EDGES + e];
        int pos = atomicAdd(&g_cursor[d], 1);
        g_col[pos] = s;
    }
}

// ---------------- W prep (ALL layers in ONE launch) ----------------
__global__ void wprep_all_kernel(
    const float* __restrict__ W1, const float* __restrict__ W2,
    const float* __restrict__ W3, const float* __restrict__ W4,
    const float* __restrict__ W5, const float* __restrict__ W6) {
    int i = blockIdx.x * blockDim.x + threadIdx.x;
    if (i >= W_TOTAL) return;
    const float* W; int off, K, Dout;
    if      (i < 8192)  { W = W1; off = 0;     K = 128; Dout = 64;  }
    else if (i < 16384) { W = W2; off = 8192;  K = 64;  Dout = 128; }
    else if (i < 49152) { W = W3; off = 16384; K = 128; Dout = 256; }
    else if (i < 81920) { W = W4; off = 49152; K = 256; Dout = 128; }
    else if (i < 90112) { W = W5; off = 81920; K = 128; Dout = 64;  }
    else                { W = W6; off = 90112; K = 64;  Dout = 64;  }
    int local = i - off;
    int k = local / Dout, n = local % Dout;
    float v = W[local];
    __nv_bfloat16 h = __float2bfloat16(v);
    float r = v - __bfloat162float(h);
    g_whi[off + n * K + k] = __bfloat16_as_ushort(h);
    g_wlo[off + n * K + k] = __bfloat16_as_ushort(__float2bfloat16(r));
}

// ---------------- warp MMA: m16n8k16 bf16 -> fp32 (sm_80+ PTX) ----------
__device__ __forceinline__ void mma16816(float* d, const uint32_t* a, const uint32_t* b) {
    asm volatile(
        "mma.sync.aligned.m16n8k16.row.col.f32.bf16.bf16.f32 "
        "{%0,%1,%2,%3}, {%4,%5,%6,%7}, {%8,%9}, {%0,%1,%2,%3};"
        : "+f"(d[0]), "+f"(d[1]), "+f"(d[2]), "+f"(d[3])
        : "r"(a[0]), "r"(a[1]), "r"(a[2]), "r"(a[3]), "r"(b[0]), "r"(b[1]));
}

// ---------------- tensor-core GEMM: C = A[NxK] @ W[KxDout] (bf16-split, 3 MMAs) ----------
// BM=128, BN in {64,128}, BK=32, 8 warps. HOUT: write fp16 (half2) instead of fp32.
template <int BN, int ACT, int SCALE, int HOUT>
__global__ void __launch_bounds__(256) mma_gemm_kernel(
    const float* __restrict__ A,
    const unsigned short* __restrict__ whi, const unsigned short* __restrict__ wlo,
    const float* __restrict__ bias, void* __restrict__ Cv,
    int K, int Dout) {
    constexpr int BK = 32;
    constexpr int SA = 40;   // row stride in halves (80B)
    constexpr int NF = BN / 16;
    __shared__ __align__(16) unsigned short Ah[128 * SA];
    __shared__ __align__(16) unsigned short Al[128 * SA];
    __shared__ __align__(16) unsigned short Bh[BN * SA];
    __shared__ __align__(16) unsigned short Bl[BN * SA];

    const int t = threadIdx.x;
    const int lane = t & 31, wid = t >> 5;
    const int g = lane >> 2, tc = lane & 3;
    const int warpRow = wid & 3, warpCol = wid >> 2;
    const int rowBase = blockIdx.x * 128;
    const int colBase = blockIdx.y * BN;

    float d[2][NF][4] = {};

    for (int kb = 0; kb < K; kb += BK) {
        // ---- stage A tile [128][BK] with fused fp32 -> bf16 hi/lo split ----
        for (int task = t; task < 128 * (BK / 8); task += 256) {
            int row = task >> 2;
            int col0 = (task & 3) * 8;
            float v[8];
            int grow = rowBase + row;
            if (grow < N_NODES) {
                const float* p = A + (size_t)grow * K + kb + col0;
                float4 x0 = *reinterpret_cast<const float4*>(p);
                float4 x1 = *reinterpret_cast<const float4*>(p + 4);
                v[0]=x0.x; v[1]=x0.y; v[2]=x0.z; v[3]=x0.w;
                v[4]=x1.x; v[5]=x1.y; v[6]=x1.z; v[7]=x1.w;
            } else {
                #pragma unroll
                for (int j = 0; j < 8; j++) v[j] = 0.f;
            }
            unsigned int hp[4], lp[4];
            #pragma unroll
            for (int j = 0; j < 4; j++) {
                __nv_bfloat16 h0 = __float2bfloat16(v[2*j]);
                __nv_bfloat16 h1 = __float2bfloat16(v[2*j+1]);
                float r0 = v[2*j]   - __bfloat162float(h0);
                float r1 = v[2*j+1] - __bfloat162float(h1);
                hp[j] = (unsigned int)__bfloat16_as_ushort(h0)
                      | ((unsigned int)__bfloat16_as_ushort(h1) << 16);
                lp[j] = (unsigned int)__bfloat16_as_ushort(__float2bfloat16(r0))
                      | ((unsigned int)__bfloat16_as_ushort(__float2bfloat16(r1)) << 16);
            }
            *reinterpret_cast<uint4*>(&Ah[row * SA + col0]) = make_uint4(hp[0],hp[1],hp[2],hp[3]);
            *reinterpret_cast<uint4*>(&Al[row * SA + col0]) = make_uint4(lp[0],lp[1],lp[2],lp[3]);
        }
        // ---- stage B tile [BN][BK] from pre-split W^T ----
        for (int task = t; task < BN * (BK / 8); task += 256) {
            int n = task >> 2;
            int col0 = (task & 3) * 8;
            size_t src = (size_t)(colBase + n) * K + kb + col0;
            *reinterpret_cast<uint4*>(&Bh[n * SA + col0]) =
                *reinterpret_cast<const uint4*>(whi + src);
            *reinterpret_cast<uint4*>(&Bl[n * SA + col0]) =
                *reinterpret_cast<const uint4*>(wlo + src);
        }
        __syncthreads();

        #pragma unroll
        for (int ks = 0; ks < 2; ks++) {
            const int kk = ks * 16;
            uint32_t ahf[2][4], alf[2][4];
            #pragma unroll
            for (int i = 0; i < 2; i++) {
                int r0 = warpRow * 32 + i * 16 + g;
                uint2 x = *reinterpret_cast<const uint2*>(&Ah[r0 * SA + kk + tc * 4]);
                uint2 y = *reinterpret_cast<const uint2*>(&Ah[(r0 + 8) * SA + kk + tc * 4]);
                ahf[i][0] = x.x; ahf[i][2] = x.y; ahf[i][1] = y.x; ahf[i][3] = y.y;
                uint2 xl = *reinterpret_cast<const uint2*>(&Al[r0 * SA + kk + tc * 4]);
                uint2 yl = *reinterpret_cast<const uint2*>(&Al[(r0 + 8) * SA + kk + tc * 4]);
                alf[i][0] = xl.x; alf[i][2] = xl.y; alf[i][1] = yl.x; alf[i][3] = yl.y;
            }
            #pragma unroll
            for (int j = 0; j < NF; j++) {
                int n = warpCol * (BN / 2) + j * 8 + g;
                uint32_t bhf[2], blf[2];
                uint2 x = *reinterpret_cast<const uint2*>(&Bh[n * SA + kk + tc * 4]);
                bhf[0] = x.x; bhf[1] = x.y;
                uint2 y = *reinterpret_cast<const uint2*>(&Bl[n * SA + kk + tc * 4]);
                blf[0] = y.x; blf[1] = y.y;
                #pragma unroll
                for (int i = 0; i < 2; i++) {
                    mma16816(d[i][j], ahf[i], bhf);
                    mma16816(d[i][j], alf[i], bhf);
                    mma16816(d[i][j], ahf[i], blf);
                }
            }
        }
        __syncthreads();
    }

    // ---- epilogue ----
    #pragma unroll
    for (int i = 0; i < 2; i++) {
        int r0 = rowBase + warpRow * 32 + i * 16 + g;
        int r1 = r0 + 8;
        float s0 = 1.0f, s1 = 1.0f;
        if (SCALE) {
            if (r0 < N_NODES) s0 = g_dinv[r0];
            if (r1 < N_NODES) s1 = g_dinv[r1];
        }
        #pragma unroll
        for (int j = 0; j < NF; j++) {
            int col = colBase + warpCol * (BN / 2) + j * 8 + tc * 2;
            float b0 = 0.f, b1 = 0.f;
            if (bias) { b0 = bias[col]; b1 = bias[col + 1]; }
            float v0 = d[i][j][0] + b0, v1 = d[i][j][1] + b1;
            float v2 = d[i][j][2] + b0, v3 = d[i][j][3] + b1;
            if (ACT == 1) {
                v0 = fmaxf(v0, 0.f); v1 = fmaxf(v1, 0.f);
                v2 = fmaxf(v2, 0.f); v3 = fmaxf(v3, 0.f);
            }
            if (HOUT) {
                if (r0 < N_NODES)
                    *reinterpret_cast<__half2*>((__half*)Cv + (size_t)r0 * Dout + col) =
                        __floats2half2_rn(v0 * s0, v1 * s0);
                if (r1 < N_NODES)
                    *reinterpret_cast<__half2*>((__half*)Cv + (size_t)r1 * Dout + col) =
                        __floats2half2_rn(v2 * s1, v3 * s1);
            } else {
                if (r0 < N_NODES)
                    *reinterpret_cast<float2*>((float*)Cv + (size_t)r0 * Dout + col) =
                        make_float2(v0 * s0, v1 * s0);
                if (r1 < N_NODES)
                    *reinterpret_cast<float2*>((float*)Cv + (size_t)r1 * Dout + col) =
                        make_float2(v2 * s1, v3 * s1);
            }
        }
    }
}

// ---------------- Aggregation (separable norm, fp16 gather) ----------------
// in: fp16 [N][64]; out fp16 (OUTH=1) or fp32. Accumulate fp32.
template <int ACT, int PRESCALE, int OUTH>  // ACT: 0 none, 1 relu, 2 sigmoid
__global__ void __launch_bounds__(256) agg64h_kernel(
    const __half* __restrict__ in, void* __restrict__ out,
    const float* __restrict__ bias) {
    int warp = (blockIdx.x * blockDim.x + threadIdx.x) >> 5;
    if (warp >= N_NODES) return;
    int lane = threadIdx.x & 31;
    const int off = lane * 2;

    float2 s = __half22float2(*reinterpret_cast<const __half2*>(in + (size_t)warp * 64 + off));
    float ax = s.x, ay = s.y;

    int e = g_rowbeg[warp], end = g_rowend[warp];
    for (; e + 4 <= end; e += 4) {
        int s0 = g_col[e], s1 = g_col[e+1], s2 = g_col[e+2], s3 = g_col[e+3];
        float2 p0 = __half22float2(*reinterpret_cast<const __half2*>(in + (size_t)s0 * 64 + off));
        float2 p1 = __half22float2(*reinterpret_cast<const __half2*>(in + (size_t)s1 * 64 + off));
        float2 p2 = __half22float2(*reinterpret_cast<const __half2*>(in + (size_t)s2 * 64 + off));
        float2 p3 = __half22float2(*reinterpret_cast<const __half2*>(in + (size_t)s3 * 64 + off));
        ax += p0.x; ay += p0.y;
        ax += p1.x; ay += p1.y;
        ax += p2.x; ay += p2.y;
        ax += p3.x; ay += p3.y;
    }
    for (; e < end; e++) {
        float2 p = __half22float2(
            *reinterpret_cast<const __half2*>(in + (size_t)g_col[e] * 64 + off));
        ax += p.x; ay += p.y;
    }

    float dd = g_dinv[warp];
    ax *= dd; ay *= dd;
    if (bias) {
        const float2 b = *reinterpret_cast<const float2*>(bias + off);
        ax += b.x; ay += b.y;
    }
    if (ACT == 1) { ax = fmaxf(ax, 0.f); ay = fmaxf(ay, 0.f); }
    if (ACT == 2) {
        ax = 1.0f / (1.0f + expf(-ax));
        ay = 1.0f / (1.0f + expf(-ay));
    }
    if (PRESCALE) { ax *= dd; ay *= dd; }
    if (OUTH)
        *reinterpret_cast<__half2*>((__half*)out + (size_t)warp * 64 + off) =
            __floats2half2_rn(ax, ay);
    else
        *reinterpret_cast<float2*>((float*)out + (size_t)warp * 64 + off) =
            make_float2(ax, ay);
}

// in: fp16 [N][128]; out fp32. Lane owns 4 halves (8B load).
template <int ACT, int PRESCALE>
__global__ void __launch_bounds__(256) agg128h_kernel(
    const __half* __restrict__ in, float* __restrict__ out,
    const float* __restrict__ bias) {
    int warp = (blockIdx.x * blockDim.x + threadIdx.x) >> 5;
    if (warp >= N_NODES) return;
    int lane = threadIdx.x & 31;
    const int off = lane * 4;

    __half2 h0, h1;
    {
        uint2 u = *reinterpret_cast<const uint2*>(in + (size_t)warp * 128 + off);
        h0 = *reinterpret_cast<__half2*>(&u.x); h1 = *reinterpret_cast<__half2*>(&u.y);
    }
    float2 f0 = __half22float2(h0), f1 = __half22float2(h1);
    float ax = f0.x, ay = f0.y, az = f1.x, aw = f1.y;

    int e = g_rowbeg[warp], end = g_rowend[warp];
    for (; e + 4 <= end; e += 4) {
        int s0 = g_col[e], s1 = g_col[e+1], s2 = g_col[e+2], s3 = g_col[e+3];
        uint2 u0 = *reinterpret_cast<const uint2*>(in + (size_t)s0 * 128 + off);
        uint2 u1 = *reinterpret_cast<const uint2*>(in + (size_t)s1 * 128 + off);
        uint2 u2 = *reinterpret_cast<const uint2*>(in + (size_t)s2 * 128 + off);
        uint2 u3 = *reinterpret_cast<const uint2*>(in + (size_t)s3 * 128 + off);
        float2 a0 = __half22float2(*reinterpret_cast<__half2*>(&u0.x));
        float2 b0 = __half22float2(*reinterpret_cast<__half2*>(&u0.y));
        float2 a1 = __half22float2(*reinterpret_cast<__half2*>(&u1.x));
        float2 b1 = __half22float2(*reinterpret_cast<__half2*>(&u1.y));
        float2 a2 = __half22float2(*reinterpret_cast<__half2*>(&u2.x));
        float2 b2 = __half22float2(*reinterpret_cast<__half2*>(&u2.y));
        float2 a3 = __half22float2(*reinterpret_cast<__half2*>(&u3.x));
        float2 b3 = __half22float2(*reinterpret_cast<__half2*>(&u3.y));
        ax += a0.x; ay += a0.y; az += b0.x; aw += b0.y;
        ax += a1.x; ay += a1.y; az += b1.x; aw += b1.y;
        ax += a2.x; ay += a2.y; az += b2.x; aw += b2.y;
        ax += a3.x; ay += a3.y; az += b3.x; aw += b3.y;
    }
    for (; e < end; e++) {
        uint2 u = *reinterpret_cast<const uint2*>(in + (size_t)g_col[e] * 128 + off);
        float2 a = __half22float2(*reinterpret_cast<__half2*>(&u.x));
        float2 b = __half22float2(*reinterpret_cast<__half2*>(&u.y));
        ax += a.x; ay += a.y; az += b.x; aw += b.y;
    }

    float dd = g_dinv[warp];
    ax *= dd; ay *= dd; az *= dd; aw *= dd;
    if (bias) {
        const float4 b = *reinterpret_cast<const float4*>(bias + off);
        ax += b.x; ay += b.y; az += b.z; aw += b.w;
    }
    if (ACT == 1) {
        ax = fmaxf(ax, 0.f); ay = fmaxf(ay, 0.f);
        az = fmaxf(az, 0.f); aw = fmaxf(aw, 0.f);
    }
    if (PRESCALE) { ax *= dd; ay *= dd; az *= dd; aw *= dd; }
    *reinterpret_cast<float4*>(out + (size_t)warp * 128 + off) = make_float4(ax, ay, az, aw);
}

// ---------------- launch ----------------
extern "C" void kernel_launch(void* const* d_in, const int* in_sizes, int n_in,
                              void* d_out, int out_size) {
    const float* x  = (const float*)d_in[0];
    const int*   ei = (const int*)d_in[1];   // int32! (JAX x64 disabled)
    const float* W1 = (const float*)d_in[2],  *b1 = (const float*)d_in[3];
    const float* W2 = (const float*)d_in[4],  *b2 = (const float*)d_in[5];
    const float* W3 = (const float*)d_in[6],  *b3 = (const float*)d_in[7];
    const float* W4 = (const float*)d_in[8],  *b4 = (const float*)d_in[9];
    const float* W5 = (const float*)d_in[10], *b5 = (const float*)d_in[11];
    const float* W6 = (const float*)d_in[12], *b6 = (const float*)d_in[13];
    float* out = (float*)d_out;

    float *bufA, *bufB;
    cudaGetSymbolAddress((void**)&bufA, g_bufA);
    cudaGetSymbolAddress((void**)&bufB, g_bufB);
    void *cntPtr, *totPtr;
    cudaGetSymbolAddress(&cntPtr, g_cnt);
    cudaGetSymbolAddress(&totPtr, g_total);
    unsigned short *whi, *wlo;
    cudaGetSymbolAddress((void**)&whi, g_whi);
    cudaGetSymbolAddress((void**)&wlo, g_wlo);
    __half* hA = (__half*)bufA;
    __half* hB = (__half*)bufB;

    const int TB = 256;
    const int nodeBlocks = (N_NODES + TB - 1) / TB;
    const int edgeBlocks = (N_EDGES + TB - 1) / TB;
    const int aggBlocks  = (N_NODES * 32 + TB - 1) / TB;
    const int gemmRows   = (N_NODES + 127) / 128;

    const int wo1 = 0, wo2 = 8192, wo3 = 16384, wo4 = 49152, wo5 = 81920, wo6 = 90112;

    // ---- preprocessing: CSR + W split/transpose ----
    cudaMemsetAsync(cntPtr, 0, N_NODES * sizeof(int));
    cudaMemsetAsync(totPtr, 0, sizeof(int));
    hist_kernel<<<edgeBlocks, TB>>>(ei);
    alloc_kernel<<<nodeBlocks, TB>>>();
    scatter_kernel<<<edgeBlocks, TB>>>(ei);
    wprep_all_kernel<<<(W_TOTAL + TB - 1) / TB, TB>>>(W1, W2, W3, W4, W5, W6);

    // L1: g1 = fp16( dinv .* (x@W1) ); agg1: a1 = fp16( dinv.*relu(dinv*sum + b1) )
    mma_gemm_kernel<64,0,1,1><<<dim3(gemmRows, 1), TB>>>(x, whi + wo1, wlo + wo1, nullptr, hA, 128, 64);
    agg64h_kernel<1,1,1><<<aggBlocks, TB>>>(hA, hB, b1);

    // L2: agg2 (fp16 in -> fp32 out) -> GEMM bias+relu+scale -> fp16 g2
    agg64h_kernel<0,0,0><<<aggBlocks, TB>>>(hB, bufA, nullptr);
    mma_gemm_kernel<128,1,1,1><<<dim3(gemmRows, 1), TB>>>(bufA, whi + wo2, wlo + wo2, b2, hB, 64, 128);

    // L3: agg3 (fp16 in, w128 -> fp32) -> GEMM bias+relu -> fp32 (L4 GEMM input)
    agg128h_kernel<0,0><<<aggBlocks, TB>>>(hB, bufA, nullptr);
    mma_gemm_kernel<128,1,0,0><<<dim3(gemmRows, 2), TB>>>(bufA, whi + wo3, wlo + wo3, b3, bufB, 128, 256);

    // L4: GEMM scale -> fp16 g4; agg4 relu+b4 -> fp32
    mma_gemm_kernel<128,0,1,1><<<dim3(gemmRows, 1), TB>>>(bufB, whi + wo4, wlo + wo4, nullptr, hA, 256, 128);
    agg128h_kernel<1,0><<<aggBlocks, TB>>>(hA, bufB, b4);

    // L5: GEMM scale -> fp16 g5; agg5 relu+b5 -> fp32
    mma_gemm_kernel<64,0,1,1><<<dim3(gemmRows, 1), TB>>>(bufB, whi + wo5, wlo + wo5, nullptr, hA, 128, 64);
    agg64h_kernel<1,0,0><<<aggBlocks, TB>>>(hA, bufB, b5);

    // L6: GEMM scale -> fp16 g6; agg6 sigmoid+b6 -> fp32 d_out
    mma_gemm_kernel<64,0,1,1><<<dim3(gemmRows, 1), TB>>>(bufB, whi + wo6, wlo + wo6, nullptr, hA, 64, 64);
    agg64h_kernel<2,0,0><<<aggBlocks, TB>>>(hA, out, b6);
}

// round 15
// speedup vs baseline: 1.1924x; 1.1579x over previous
#include <cuda_runtime.h>
#include <cuda_fp16.h>
#include <math.h>
#include <stdint.h>

#define N_NODES 50000
#define N_EDGES 800000
#define W_TOTAL 94208  // sum of K*Dout over 6 layers

// ---------------- static device scratch (allocation-free rule) ----------------
__device__ float g_bufA[N_NODES * 256];
__device__ float g_bufB[N_NODES * 256];
__device__ int   g_rowbeg[N_NODES];
__device__ int   g_rowend[N_NODES];
__device__ int   g_cursor[N_NODES];
__device__ int   g_cnt[N_NODES];
__device__ float g_dinv[N_NODES];
__device__ int   g_col[N_EDGES];
__device__ int   g_total;
__device__ unsigned short g_whi[W_TOTAL];  // fp16 hi, transposed [Dout][K]
__device__ unsigned short g_wlo[W_TOTAL];  // fp16 lo (residual)

__device__ __forceinline__ uint32_t h2_as_u32(__half2 h) {
    return *reinterpret_cast<uint32_t*>(&h);
}

// ---------------- CSR build (scan-free) ----------------
__global__ void hist_kernel(const int* __restrict__ ei) {
    int e = blockIdx.x * blockDim.x + threadIdx.x;
    if (e < N_EDGES) atomicAdd(&g_cnt[ei[N_EDGES + e]], 1);
}

__global__ void alloc_kernel() {
    int i = blockIdx.x * blockDim.x + threadIdx.x;
    if (i < N_NODES) {
        int c = g_cnt[i];
        g_dinv[i] = rsqrtf((float)c + 1.0f);
        int beg = atomicAdd(&g_total, c);
        g_rowbeg[i] = beg;
        g_rowend[i] = beg + c;
        g_cursor[i] = beg;
    }
}

__global__ void scatter_kernel(const int* __restrict__ ei) {
    int e = blockIdx.x * blockDim.x + threadIdx.x;
    if (e < N_EDGES) {
        int s = ei[e];
        int d = ei[N_EDGES + e];
        int pos = atomicAdd(&g_cursor[d], 1);
        g_col[pos] = s;
    }
}

// ---------------- W prep: fp32 [K][Dout] -> fp16 hi/lo transposed [Dout][K] ----------------
__global__ void wprep_all_kernel(
    const float* __restrict__ W1, const float* __restrict__ W2,
    const float* __restrict__ W3, const float* __restrict__ W4,
    const float* __restrict__ W5, const float* __restrict__ W6) {
    int i = blockIdx.x * blockDim.x + threadIdx.x;
    if (i >= W_TOTAL) return;
    const float* W; int off, K, Dout;
    if      (i < 8192)  { W = W1; off = 0;     K = 128; Dout = 64;  }
    else if (i < 16384) { W = W2; off = 8192;  K = 64;  Dout = 128; }
    else if (i < 49152) { W = W3; off = 16384; K = 128; Dout = 256; }
    else if (i < 81920) { W = W4; off = 49152; K = 256; Dout = 128; }
    else if (i < 90112) { W = W5; off = 81920; K = 128; Dout = 64;  }
    else                { W = W6; off = 90112; K = 64;  Dout = 64;  }
    int local = i - off;
    int k = local / Dout, n = local % Dout;
    float v = W[local];
    __half h = __float2half_rn(v);
    float r = v - __half2float(h);
    g_whi[off + n * K + k] = __half_as_ushort(h);
    g_wlo[off + n * K + k] = __half_as_ushort(__float2half_rn(r));
}

// ---------------- warp MMA: m16n8k16 fp16 -> fp32 (sm_80+ PTX) ----------
__device__ __forceinline__ void mma16816(float* d, const uint32_t* a, const uint32_t* b) {
    asm volatile(
        "mma.sync.aligned.m16n8k16.row.col.f32.f16.f16.f32 "
        "{%0,%1,%2,%3}, {%4,%5,%6,%7}, {%8,%9}, {%0,%1,%2,%3};"
        : "+f"(d[0]), "+f"(d[1]), "+f"(d[2]), "+f"(d[3])
        : "r"(a[0]), "r"(a[1]), "r"(a[2]), "r"(a[3]), "r"(b[0]), "r"(b[1]));
}

// ---------------- tensor-core GEMM: C = A[NxK] @ W[KxDout] (fp16 A exact, W hi/lo, 2 MMAs) ---
// BM=128, BN in {64,128}, BK=32, 8 warps. AFP32: A source is fp32 (round to fp16 in staging);
// otherwise A source is fp16 (exact). HOUT: fp16 output; else fp32.
template <int BN, int ACT, int SCALE, int HOUT, int AFP32>
__global__ void __launch_bounds__(256) mma_gemm_kernel(
    const void* __restrict__ Av,
    const unsigned short* __restrict__ whi, const unsigned short* __restrict__ wlo,
    const float* __restrict__ bias, void* __restrict__ Cv,
    int K, int Dout) {
    constexpr int BK = 32;
    constexpr int SA = 40;   // row stride in halves (80B)
    constexpr int NF = BN / 16;
    __shared__ __align__(16) unsigned short Ah[128 * SA];
    __shared__ __align__(16) unsigned short Bh[BN * SA];
    __shared__ __align__(16) unsigned short Bl[BN * SA];

    const int t = threadIdx.x;
    const int lane = t & 31, wid = t >> 5;
    const int g = lane >> 2, tc = lane & 3;
    const int warpRow = wid & 3, warpCol = wid >> 2;
    const int rowBase = blockIdx.x * 128;
    const int colBase = blockIdx.y * BN;

    float d[2][NF][4] = {};

    for (int kb = 0; kb < K; kb += BK) {
        // ---- stage A tile [128][BK] (fp16; convert from fp32 if AFP32) ----
        for (int task = t; task < 128 * (BK / 8); task += 256) {
            int row = task >> 2;             // BK/8 == 4
            int col0 = (task & 3) * 8;
            int grow = rowBase + row;
            uint4 packed = make_uint4(0, 0, 0, 0);
            if (grow < N_NODES) {
                if (AFP32) {
                    const float* p = (const float*)Av + (size_t)grow * K + kb + col0;
                    float4 x0 = *reinterpret_cast<const float4*>(p);
                    float4 x1 = *reinterpret_cast<const float4*>(p + 4);
                    packed.x = h2_as_u32(__floats2half2_rn(x0.x, x0.y));
                    packed.y = h2_as_u32(__floats2half2_rn(x0.z, x0.w));
                    packed.z = h2_as_u32(__floats2half2_rn(x1.x, x1.y));
                    packed.w = h2_as_u32(__floats2half2_rn(x1.z, x1.w));
                } else {
                    packed = *reinterpret_cast<const uint4*>(
                        (const __half*)Av + (size_t)grow * K + kb + col0);
                }
            }
            *reinterpret_cast<uint4*>(&Ah[row * SA + col0]) = packed;
        }
        // ---- stage B tile [BN][BK] from pre-split W^T ([Dout][K] fp16) ----
        for (int task = t; task < BN * (BK / 8); task += 256) {
            int n = task >> 2;
            int col0 = (task & 3) * 8;
            size_t src = (size_t)(colBase + n) * K + kb + col0;
            *reinterpret_cast<uint4*>(&Bh[n * SA + col0]) =
                *reinterpret_cast<const uint4*>(whi + src);
            *reinterpret_cast<uint4*>(&Bl[n * SA + col0]) =
                *reinterpret_cast<const uint4*>(wlo + src);
        }
        __syncthreads();

        #pragma unroll
        for (int ks = 0; ks < 2; ks++) {
            const int kk = ks * 16;
            uint32_t ahf[2][4];
            #pragma unroll
            for (int i = 0; i < 2; i++) {
                int r0 = warpRow * 32 + i * 16 + g;
                uint2 x = *reinterpret_cast<const uint2*>(&Ah[r0 * SA + kk + tc * 4]);
                uint2 y = *reinterpret_cast<const uint2*>(&Ah[(r0 + 8) * SA + kk + tc * 4]);
                ahf[i][0] = x.x; ahf[i][2] = x.y; ahf[i][1] = y.x; ahf[i][3] = y.y;
            }
            #pragma unroll
            for (int j = 0; j < NF; j++) {
                int n = warpCol * (BN / 2) + j * 8 + g;
                uint32_t bhf[2], blf[2];
                uint2 x = *reinterpret_cast<const uint2*>(&Bh[n * SA + kk + tc * 4]);
                bhf[0] = x.x; bhf[1] = x.y;
                uint2 y = *reinterpret_cast<const uint2*>(&Bl[n * SA + kk + tc * 4]);
                blf[0] = y.x; blf[1] = y.y;
                #pragma unroll
                for (int i = 0; i < 2; i++) {
                    mma16816(d[i][j], ahf[i], bhf);
                    mma16816(d[i][j], ahf[i], blf);
                }
            }
        }
        __syncthreads();
    }

    // ---- epilogue ----
    #pragma unroll
    for (int i = 0; i < 2; i++) {
        int r0 = rowBase + warpRow * 32 + i * 16 + g;
        int r1 = r0 + 8;
        float s0 = 1.0f, s1 = 1.0f;
        if (SCALE) {
            if (r0 < N_NODES) s0 = g_dinv[r0];
            if (r1 < N_NODES) s1 = g_dinv[r1];
        }
        #pragma unroll
        for (int j = 0; j < NF; j++) {
            int col = colBase + warpCol * (BN / 2) + j * 8 + tc * 2;
            float b0 = 0.f, b1 = 0.f;
            if (bias) { b0 = bias[col]; b1 = bias[col + 1]; }
            float v0 = d[i][j][0] + b0, v1 = d[i][j][1] + b1;
            float v2 = d[i][j][2] + b0, v3 = d[i][j][3] + b1;
            if (ACT == 1) {
                v0 = fmaxf(v0, 0.f); v1 = fmaxf(v1, 0.f);
                v2 = fmaxf(v2, 0.f); v3 = fmaxf(v3, 0.f);
            }
            if (HOUT) {
                if (r0 < N_NODES)
                    *reinterpret_cast<__half2*>((__half*)Cv + (size_t)r0 * Dout + col) =
                        __floats2half2_rn(v0 * s0, v1 * s0);
                if (r1 < N_NODES)
                    *reinterpret_cast<__half2*>((__half*)Cv + (size_t)r1 * Dout + col) =
                        __floats2half2_rn(v2 * s1, v3 * s1);
            } else {
                if (r0 < N_NODES)
                    *reinterpret_cast<float2*>((float*)Cv + (size_t)r0 * Dout + col) =
                        make_float2(v0 * s0, v1 * s0);
                if (r1 < N_NODES)
                    *reinterpret_cast<float2*>((float*)Cv + (size_t)r1 * Dout + col) =
                        make_float2(v2 * s1, v3 * s1);
            }
        }
    }
}

// ---------------- Aggregation (separable norm, fp16 gather, fp32 accumulate) --------------
// in: fp16 [N][64]; OUTH: fp16 out, else fp32 out.
template <int ACT, int PRESCALE, int OUTH>  // ACT: 0 none, 1 relu, 2 sigmoid
__global__ void __launch_bounds__(256) agg64h_kernel(
    const __half* __restrict__ in, void* __restrict__ out,
    const float* __restrict__ bias) {
    int warp = (blockIdx.x * blockDim.x + threadIdx.x) >> 5;
    if (warp >= N_NODES) return;
    int lane = threadIdx.x & 31;
    const int off = lane * 2;

    float2 s = __half22float2(*reinterpret_cast<const __half2*>(in + (size_t)warp * 64 + off));
    float ax = s.x, ay = s.y;

    int e = g_rowbeg[warp], end = g_rowend[warp];
    for (; e + 4 <= end; e += 4) {
        int s0 = g_col[e], s1 = g_col[e+1], s2 = g_col[e+2], s3 = g_col[e+3];
        float2 p0 = __half22float2(*reinterpret_cast<const __half2*>(in + (size_t)s0 * 64 + off));
        float2 p1 = __half22float2(*reinterpret_cast<const __half2*>(in + (size_t)s1 * 64 + off));
        float2 p2 = __half22float2(*reinterpret_cast<const __half2*>(in + (size_t)s2 * 64 + off));
        float2 p3 = __half22float2(*reinterpret_cast<const __half2*>(in + (size_t)s3 * 64 + off));
        ax += p0.x; ay += p0.y;
        ax += p1.x; ay += p1.y;
        ax += p2.x; ay += p2.y;
        ax += p3.x; ay += p3.y;
    }
    for (; e < end; e++) {
        float2 p = __half22float2(
            *reinterpret_cast<const __half2*>(in + (size_t)g_col[e] * 64 + off));
        ax += p.x; ay += p.y;
    }

    float dd = g_dinv[warp];
    ax *= dd; ay *= dd;
    if (bias) {
        const float2 b = *reinterpret_cast<const float2*>(bias + off);
        ax += b.x; ay += b.y;
    }
    if (ACT == 1) { ax = fmaxf(ax, 0.f); ay = fmaxf(ay, 0.f); }
    if (ACT == 2) {
        ax = 1.0f / (1.0f + expf(-ax));
        ay = 1.0f / (1.0f + expf(-ay));
    }
    if (PRESCALE) { ax *= dd; ay *= dd; }
    if (OUTH)
        *reinterpret_cast<__half2*>((__half*)out + (size_t)warp * 64 + off) =
            __floats2half2_rn(ax, ay);
    else
        *reinterpret_cast<float2*>((float*)out + (size_t)warp * 64 + off) =
            make_float2(ax, ay);
}

// in: fp16 [N][128]; OUTH: fp16 out, else fp32 out. Lane owns 4 halves (8B).
template <int ACT, int PRESCALE, int OUTH>
__global__ void __launch_bounds__(256) agg128h_kernel(
    const __half* __restrict__ in, void* __restrict__ out,
    const float* __restrict__ bias) {
    int warp = (blockIdx.x * blockDim.x + threadIdx.x) >> 5;
    if (warp >= N_NODES) return;
    int lane = threadIdx.x & 31;
    const int off = lane * 4;

    float ax, ay, az, aw;
    {
        uint2 u = *reinterpret_cast<const uint2*>(in + (size_t)warp * 128 + off);
        float2 f0 = __half22float2(*reinterpret_cast<__half2*>(&u.x));
        float2 f1 = __half22float2(*reinterpret_cast<__half2*>(&u.y));
        ax = f0.x; ay = f0.y; az = f1.x; aw = f1.y;
    }

    int e = g_rowbeg[warp], end = g_rowend[warp];
    for (; e + 4 <= end; e += 4) {
        int s0 = g_col[e], s1 = g_col[e+1], s2 = g_col[e+2], s3 = g_col[e+3];
        uint2 u0 = *reinterpret_cast<const uint2*>(in + (size_t)s0 * 128 + off);
        uint2 u1 = *reinterpret_cast<const uint2*>(in + (size_t)s1 * 128 + off);
        uint2 u2 = *reinterpret_cast<const uint2*>(in + (size_t)s2 * 128 + off);
        uint2 u3 = *reinterpret_cast<const uint2*>(in + (size_t)s3 * 128 + off);
        float2 a0 = __half22float2(*reinterpret_cast<__half2*>(&u0.x));
        float2 b0 = __half22float2(*reinterpret_cast<__half2*>(&u0.y));
        float2 a1 = __half22float2(*reinterpret_cast<__half2*>(&u1.x));
        float2 b1 = __half22float2(*reinterpret_cast<__half2*>(&u1.y));
        float2 a2 = __half22float2(*reinterpret_cast<__half2*>(&u2.x));
        float2 b2 = __half22float2(*reinterpret_cast<__half2*>(&u2.y));
        float2 a3 = __half22float2(*reinterpret_cast<__half2*>(&u3.x));
        float2 b3 = __half22float2(*reinterpret_cast<__half2*>(&u3.y));
        ax += a0.x; ay += a0.y; az += b0.x; aw += b0.y;
        ax += a1.x; ay += a1.y; az += b1.x; aw += b1.y;
        ax += a2.x; ay += a2.y; az += b2.x; aw += b2.y;
        ax += a3.x; ay += a3.y; az += b3.x; aw += b3.y;
    }
    for (; e < end; e++) {
        uint2 u = *reinterpret_cast<const uint2*>(in + (size_t)g_col[e] * 128 + off);
        float2 a = __half22float2(*reinterpret_cast<__half2*>(&u.x));
        float2 b = __half22float2(*reinterpret_cast<__half2*>(&u.y));
        ax += a.x; ay += a.y; az += b.x; aw += b.y;
    }

    float dd = g_dinv[warp];
    ax *= dd; ay *= dd; az *= dd; aw *= dd;
    if (bias) {
        const float4 b = *reinterpret_cast<const float4*>(bias + off);
        ax += b.x; ay += b.y; az += b.z; aw += b.w;
    }
    if (ACT == 1) {
        ax = fmaxf(ax, 0.f); ay = fmaxf(ay, 0.f);
        az = fmaxf(az, 0.f); aw = fmaxf(aw, 0.f);
    }
    if (PRESCALE) { ax *= dd; ay *= dd; az *= dd; aw *= dd; }
    if (OUTH) {
        uint2 u;
        u.x = h2_as_u32(__floats2half2_rn(ax, ay));
        u.y = h2_as_u32(__floats2half2_rn(az, aw));
        *reinterpret_cast<uint2*>((__half*)out + (size_t)warp * 128 + off) = u;
    } else {
        *reinterpret_cast<float4*>((float*)out + (size_t)warp * 128 + off) =
            make_float4(ax, ay, az, aw);
    }
}

// ---------------- launch ----------------
extern "C" void kernel_launch(void* const* d_in, const int* in_sizes, int n_in,
                              void* d_out, int out_size) {
    const float* x  = (const float*)d_in[0];
    const int*   ei = (const int*)d_in[1];   // int32! (JAX x64 disabled)
    const float* W1 = (const float*)d_in[2],  *b1 = (const float*)d_in[3];
    const float* W2 = (const float*)d_in[4],  *b2 = (const float*)d_in[5];
    const float* W3 = (const float*)d_in[6],  *b3 = (const float*)d_in[7];
    const float* W4 = (const float*)d_in[8],  *b4 = (const float*)d_in[9];
    const float* W5 = (const float*)d_in[10], *b5 = (const float*)d_in[11];
    const float* W6 = (const float*)d_in[12], *b6 = (const float*)d_in[13];
    float* out = (float*)d_out;

    float *bufA, *bufB;
    cudaGetSymbolAddress((void**)&bufA, g_bufA);
    cudaGetSymbolAddress((void**)&bufB, g_bufB);
    void *cntPtr, *totPtr;
    cudaGetSymbolAddress(&cntPtr, g_cnt);
    cudaGetSymbolAddress(&totPtr, g_total);
    unsigned short *whi, *wlo;
    cudaGetSymbolAddress((void**)&whi, g_whi);
    cudaGetSymbolAddress((void**)&wlo, g_wlo);
    __half* hA = (__half*)bufA;
    __half* hB = (__half*)bufB;

    const int TB = 256;
    const int nodeBlocks = (N_NODES + TB - 1) / TB;
    const int edgeBlocks = (N_EDGES + TB - 1) / TB;
    const int aggBlocks  = (N_NODES * 32 + TB - 1) / TB;
    const int gemmRows   = (N_NODES + 127) / 128;

    const int wo1 = 0, wo2 = 8192, wo3 = 16384, wo4 = 49152, wo5 = 81920, wo6 = 90112;

    // ---- preprocessing: CSR + W split/transpose ----
    cudaMemsetAsync(cntPtr, 0, N_NODES * sizeof(int));
    cudaMemsetAsync(totPtr, 0, sizeof(int));
    hist_kernel<<<edgeBlocks, TB>>>(ei);
    alloc_kernel<<<nodeBlocks, TB>>>();
    scatter_kernel<<<edgeBlocks, TB>>>(ei);
    wprep_all_kernel<<<(W_TOTAL + TB - 1) / TB, TB>>>(W1, W2, W3, W4, W5, W6);

    // L1: g1 = fp16( dinv .* (x@W1) )  [x rounded to fp16 in staging]
    mma_gemm_kernel<64,0,1,1,1><<<dim3(gemmRows, 1), TB>>>(x, whi + wo1, wlo + wo1, nullptr, hA, 128, 64);
    agg64h_kernel<1,1,1><<<aggBlocks, TB>>>(hA, hB, b1);

    // L2: agg2 -> GEMM bias+relu+scale -> fp16 g2
    agg64h_kernel<0,0,1><<<aggBlocks, TB>>>(hB, hA, nullptr);
    mma_gemm_kernel<128,1,1,1,0><<<dim3(gemmRows, 1), TB>>>(hA, whi + wo2, wlo + wo2, b2, hB, 64, 128);

    // L3: agg3 -> GEMM bias+relu -> fp16 (L4 GEMM input)
    agg128h_kernel<0,0,1><<<aggBlocks, TB>>>(hB, hA, nullptr);
    mma_gemm_kernel<128,1,0,1,0><<<dim3(gemmRows, 2), TB>>>(hA, whi + wo3, wlo + wo3, b3, hB, 128, 256);

    // L4: GEMM scale -> fp16 g4; agg4 relu+b4 -> fp16
    mma_gemm_kernel<128,0,1,1,0><<<dim3(gemmRows, 1), TB>>>(hB, whi + wo4, wlo + wo4, nullptr, hA, 256, 128);
    agg128h_kernel<1,0,1><<<aggBlocks, TB>>>(hA, hB, b4);

    // L5: GEMM scale -> fp16 g5; agg5 relu+b5 -> fp16
    mma_gemm_kernel<64,0,1,1,0><<<dim3(gemmRows, 1), TB>>>(hB, whi + wo5, wlo + wo5, nullptr, hA, 128, 64);
    agg64h_kernel<1,0,1><<<aggBlocks, TB>>>(hA, hB, b5);

    // L6: GEMM scale -> fp16 g6; agg6 sigmoid+b6 -> fp32 d_out
    mma_gemm_kernel<64,0,1,1,0><<<dim3(gemmRows, 1), TB>>>(hB, whi + wo6, wlo + wo6, nullptr, hA, 64, 64);
    agg64h_kernel<2,0,0><<<aggBlocks, TB>>>(hA, out, b6);
}

// round 16
// speedup vs baseline: 1.2261x; 1.0283x over previous
#include <cuda_runtime.h>
#include <cuda_fp16.h>
#include <math.h>
#include <stdint.h>

#define N_NODES 50000
#define N_EDGES 800000
#define W_TOTAL 94208  // sum of K*Dout over 6 layers

// ---------------- static device scratch (allocation-free rule) ----------------
__device__ float g_bufA[N_NODES * 256];
__device__ float g_bufB[N_NODES * 256];
__device__ int   g_rowbeg[N_NODES];
__device__ int   g_rowend[N_NODES];
__device__ int   g_cursor[N_NODES];
__device__ int   g_cnt[N_NODES];
__device__ float g_dinv[N_NODES];
__device__ int   g_col[N_EDGES];
__device__ int   g_total;
__device__ unsigned short g_whi[W_TOTAL];  // fp16 hi, transposed [Dout][K]
__device__ unsigned short g_wlo[W_TOTAL];  // fp16 lo (residual)

__device__ __forceinline__ uint32_t h2_as_u32(__half2 h) {
    return *reinterpret_cast<uint32_t*>(&h);
}

// ---------------- W prep + counter zeroing (ONE launch, removes 2 memsets) ---------------
__global__ void wprep_zero_kernel(
    const float* __restrict__ W1, const float* __restrict__ W2,
    const float* __restrict__ W3, const float* __restrict__ W4,
    const float* __restrict__ W5, const float* __restrict__ W6) {
    int i = blockIdx.x * blockDim.x + threadIdx.x;
    if (i < N_NODES) g_cnt[i] = 0;
    if (i == 0) g_total = 0;
    if (i >= W_TOTAL) return;
    const float* W; int off, K, Dout;
    if      (i < 8192)  { W = W1; off = 0;     K = 128; Dout = 64;  }
    else if (i < 16384) { W = W2; off = 8192;  K = 64;  Dout = 128; }
    else if (i < 49152) { W = W3; off = 16384; K = 128; Dout = 256; }
    else if (i < 81920) { W = W4; off = 49152; K = 256; Dout = 128; }
    else if (i < 90112) { W = W5; off = 81920; K = 128; Dout = 64;  }
    else                { W = W6; off = 90112; K = 64;  Dout = 64;  }
    int local = i - off;
    int k = local / Dout, n = local % Dout;
    float v = W[local];
    __half h = __float2half_rn(v);
    float r = v - __half2float(h);
    g_whi[off + n * K + k] = __half_as_ushort(h);
    g_wlo[off + n * K + k] = __half_as_ushort(__float2half_rn(r));
}

// ---------------- CSR build (scan-free) ----------------
__global__ void hist_kernel(const int* __restrict__ ei) {
    int e = blockIdx.x * blockDim.x + threadIdx.x;
    if (e < N_EDGES) atomicAdd(&g_cnt[ei[N_EDGES + e]], 1);
}

__global__ void alloc_kernel() {
    int i = blockIdx.x * blockDim.x + threadIdx.x;
    if (i < N_NODES) {
        int c = g_cnt[i];
        g_dinv[i] = rsqrtf((float)c + 1.0f);
        int beg = atomicAdd(&g_total, c);
        g_rowbeg[i] = beg;
        g_rowend[i] = beg + c;
        g_cursor[i] = beg;
    }
}

__global__ void scatter_kernel(const int* __restrict__ ei) {
    int e = blockIdx.x * blockDim.x + threadIdx.x;
    if (e < N_EDGES) {
        int s = ei[e];
        int d = ei[N_EDGES + e];
        int pos = atomicAdd(&g_cursor[d], 1);
        g_col[pos] = s;
    }
}

// ---------------- warp MMA: m16n8k16 fp16 -> fp32 (sm_80+ PTX) ----------
__device__ __forceinline__ void mma16816(float* d, const uint32_t* a, const uint32_t* b) {
    asm volatile(
        "mma.sync.aligned.m16n8k16.row.col.f32.f16.f16.f32 "
        "{%0,%1,%2,%3}, {%4,%5,%6,%7}, {%8,%9}, {%0,%1,%2,%3};"
        : "+f"(d[0]), "+f"(d[1]), "+f"(d[2]), "+f"(d[3])
        : "r"(a[0]), "r"(a[1]), "r"(a[2]), "r"(a[3]), "r"(b[0]), "r"(b[1]));
}

// ---------------- tensor-core GEMM: C = A[NxK] @ W[KxDout] (fp16 A, W hi/lo, 2 MMAs) -----
// BM=128, BN in {64,128}, BK=32, 8 warps. Double-buffered smem with register prefetch:
// one __syncthreads per K-chunk; global loads of chunk c+1 overlap MMA of chunk c.
#define MMA_SMEM(BN) ((2 * 128 + 4 * (BN)) * 40 * 2)

template <int BN, int ACT, int SCALE, int HOUT, int AFP32>
__global__ void __launch_bounds__(256) mma_gemm_kernel(
    const void* __restrict__ Av,
    const unsigned short* __restrict__ whi, const unsigned short* __restrict__ wlo,
    const float* __restrict__ bias, void* __restrict__ Cv,
    int K, int Dout) {
    constexpr int BK = 32;
    constexpr int SA = 40;   // row stride in halves (80B)
    constexpr int NF = BN / 16;
    constexpr int ASZ = 128 * SA;
    constexpr int BSZ = BN * SA;
    extern __shared__ __align__(16) unsigned short sm[];
    unsigned short* Ah = sm;                 // [2][ASZ]
    unsigned short* Bh = sm + 2 * ASZ;       // [2][BSZ]
    unsigned short* Bl = Bh + 2 * BSZ;       // [2][BSZ]

    const int t = threadIdx.x;
    const int lane = t & 31, wid = t >> 5;
    const int g = lane >> 2, tc = lane & 3;
    const int warpRow = wid & 3, warpCol = wid >> 2;
    const int rowBase = blockIdx.x * 128;
    const int colBase = blockIdx.y * BN;

    // staging assignments: A rows (t>>2) and (t>>2)+64; B row (t>>2) (+64 if BN=128)
    const int sr = t >> 2;
    const int ac = (t & 3) * 8;

    auto loadA = [&](int row, int kb) {
        int grow = rowBase + row;
        uint4 packed = make_uint4(0, 0, 0, 0);
        if (grow < N_NODES) {
            if (AFP32) {
                const float* p = (const float*)Av + (size_t)grow * K + kb + ac;
                float4 x0 = *reinterpret_cast<const float4*>(p);
                float4 x1 = *reinterpret_cast<const float4*>(p + 4);
                packed.x = h2_as_u32(__floats2half2_rn(x0.x, x0.y));
                packed.y = h2_as_u32(__floats2half2_rn(x0.z, x0.w));
                packed.z = h2_as_u32(__floats2half2_rn(x1.x, x1.y));
                packed.w = h2_as_u32(__floats2half2_rn(x1.z, x1.w));
            } else {
                packed = *reinterpret_cast<const uint4*>(
                    (const __half*)Av + (size_t)grow * K + kb + ac);
            }
        }
        return packed;
    };

    float d[2][NF][4] = {};
    const int NCH = K / BK;

    // ---- prefetch + store chunk 0 ----
    uint4 a0 = loadA(sr, 0), a1 = loadA(sr + 64, 0);
    uint4 bh0, bl0, bh1, bl1;
    {
        size_t s0 = (size_t)(colBase + sr) * K + ac;
        bh0 = *reinterpret_cast<const uint4*>(whi + s0);
        bl0 = *reinterpret_cast<const uint4*>(wlo + s0);
        if (BN == 128) {
            size_t s1 = (size_t)(colBase + sr + 64) * K + ac;
            bh1 = *reinterpret_cast<const uint4*>(whi + s1);
            bl1 = *reinterpret_cast<const uint4*>(wlo + s1);
        }
    }
    *reinterpret_cast<uint4*>(&Ah[sr * SA + ac]) = a0;
    *reinterpret_cast<uint4*>(&Ah[(sr + 64) * SA + ac]) = a1;
    *reinterpret_cast<uint4*>(&Bh[sr * SA + ac]) = bh0;
    *reinterpret_cast<uint4*>(&Bl[sr * SA + ac]) = bl0;
    if (BN == 128) {
        *reinterpret_cast<uint4*>(&Bh[(sr + 64) * SA + ac]) = bh1;
        *reinterpret_cast<uint4*>(&Bl[(sr + 64) * SA + ac]) = bl1;
    }
    __syncthreads();

    for (int c = 0; c < NCH; c++) {
        const int cur = c & 1;
        const bool more = (c + 1 < NCH);
        if (more) {
            int kb = (c + 1) * BK;
            a0 = loadA(sr, kb);
            a1 = loadA(sr + 64, kb);
            size_t s0 = (size_t)(colBase + sr) * K + kb + ac;
            bh0 = *reinterpret_cast<const uint4*>(whi + s0);
            bl0 = *reinterpret_cast<const uint4*>(wlo + s0);
            if (BN == 128) {
                size_t s1 = (size_t)(colBase + sr + 64) * K + kb + ac;
                bh1 = *reinterpret_cast<const uint4*>(whi + s1);
                bl1 = *reinterpret_cast<const uint4*>(wlo + s1);
            }
        }
        const unsigned short* Ac  = Ah + cur * ASZ;
        const unsigned short* Bhc = Bh + cur * BSZ;
        const unsigned short* Blc = Bl + cur * BSZ;
        #pragma unroll
        for (int ks = 0; ks < 2; ks++) {
            const int kk = ks * 16;
            uint32_t ahf[2][4];
            #pragma unroll
            for (int i = 0; i < 2; i++) {
                int r0 = warpRow * 32 + i * 16 + g;
                uint2 x = *reinterpret_cast<const uint2*>(&Ac[r0 * SA + kk + tc * 4]);
                uint2 y = *reinterpret_cast<const uint2*>(&Ac[(r0 + 8) * SA + kk + tc * 4]);
                ahf[i][0] = x.x; ahf[i][2] = x.y; ahf[i][1] = y.x; ahf[i][3] = y.y;
            }
            #pragma unroll
            for (int j = 0; j < NF; j++) {
                int n = warpCol * (BN / 2) + j * 8 + g;
                uint32_t bhf[2], blf[2];
                uint2 x = *reinterpret_cast<const uint2*>(&Bhc[n * SA + kk + tc * 4]);
                bhf[0] = x.x; bhf[1] = x.y;
                uint2 y = *reinterpret_cast<const uint2*>(&Blc[n * SA + kk + tc * 4]);
                blf[0] = y.x; blf[1] = y.y;
                #pragma unroll
                for (int i = 0; i < 2; i++) {
                    mma16816(d[i][j], ahf[i], bhf);
                    mma16816(d[i][j], ahf[i], blf);
                }
            }
        }
        if (more) {
            const int nxt = cur ^ 1;
            *reinterpret_cast<uint4*>(&Ah[nxt * ASZ + sr * SA + ac]) = a0;
            *reinterpret_cast<uint4*>(&Ah[nxt * ASZ + (sr + 64) * SA + ac]) = a1;
            *reinterpret_cast<uint4*>(&Bh[nxt * BSZ + sr * SA + ac]) = bh0;
            *reinterpret_cast<uint4*>(&Bl[nxt * BSZ + sr * SA + ac]) = bl0;
            if (BN == 128) {
                *reinterpret_cast<uint4*>(&Bh[nxt * BSZ + (sr + 64) * SA + ac]) = bh1;
                *reinterpret_cast<uint4*>(&Bl[nxt * BSZ + (sr + 64) * SA + ac]) = bl1;
            }
        }
        __syncthreads();
    }

    // ---- epilogue ----
    #pragma unroll
    for (int i = 0; i < 2; i++) {
        int r0 = rowBase + warpRow * 32 + i * 16 + g;
        int r1 = r0 + 8;
        float s0 = 1.0f, s1 = 1.0f;
        if (SCALE) {
            if (r0 < N_NODES) s0 = g_dinv[r0];
            if (r1 < N_NODES) s1 = g_dinv[r1];
        }
        #pragma unroll
        for (int j = 0; j < NF; j++) {
            int col = colBase + warpCol * (BN / 2) + j * 8 + tc * 2;
            float b0 = 0.f, b1 = 0.f;
            if (bias) { b0 = bias[col]; b1 = bias[col + 1]; }
            float v0 = d[i][j][0] + b0, v1 = d[i][j][1] + b1;
            float v2 = d[i][j][2] + b0, v3 = d[i][j][3] + b1;
            if (ACT == 1) {
                v0 = fmaxf(v0, 0.f); v1 = fmaxf(v1, 0.f);
                v2 = fmaxf(v2, 0.f); v3 = fmaxf(v3, 0.f);
            }
            if (HOUT) {
                if (r0 < N_NODES)
                    *reinterpret_cast<__half2*>((__half*)Cv + (size_t)r0 * Dout + col) =
                        __floats2half2_rn(v0 * s0, v1 * s0);
                if (r1 < N_NODES)
                    *reinterpret_cast<__half2*>((__half*)Cv + (size_t)r1 * Dout + col) =
                        __floats2half2_rn(v2 * s1, v3 * s1);
            } else {
                if (r0 < N_NODES)
                    *reinterpret_cast<float2*>((float*)Cv + (size_t)r0 * Dout + col) =
                        make_float2(v0 * s0, v1 * s0);
                if (r1 < N_NODES)
                    *reinterpret_cast<float2*>((float*)Cv + (size_t)r1 * Dout + col) =
                        make_float2(v2 * s1, v3 * s1);
            }
        }
    }
}

// ---------------- Aggregation (separable norm, fp16 gather, fp32 accumulate) --------------
// in: fp16 [N][64]; OUTH: fp16 out, else fp32 out.
template <int ACT, int PRESCALE, int OUTH>  // ACT: 0 none, 1 relu, 2 sigmoid
__global__ void __launch_bounds__(256) agg64h_kernel(
    const __half* __restrict__ in, void* __restrict__ out,
    const float* __restrict__ bias) {
    int warp = (blockIdx.x * blockDim.x + threadIdx.x) >> 5;
    if (warp >= N_NODES) return;
    int lane = threadIdx.x & 31;
    const int off = lane * 2;

    float2 s = __half22float2(*reinterpret_cast<const __half2*>(in + (size_t)warp * 64 + off));
    float ax = s.x, ay = s.y;

    int e = g_rowbeg[warp], end = g_rowend[warp];
    for (; e + 4 <= end; e += 4) {
        int s0 = g_col[e], s1 = g_col[e+1], s2 = g_col[e+2], s3 = g_col[e+3];
        float2 p0 = __half22float2(*reinterpret_cast<const __half2*>(in + (size_t)s0 * 64 + off));
        float2 p1 = __half22float2(*reinterpret_cast<const __half2*>(in + (size_t)s1 * 64 + off));
        float2 p2 = __half22float2(*reinterpret_cast<const __half2*>(in + (size_t)s2 * 64 + off));
        float2 p3 = __half22float2(*reinterpret_cast<const __half2*>(in + (size_t)s3 * 64 + off));
        ax += p0.x; ay += p0.y;
        ax += p1.x; ay += p1.y;
        ax += p2.x; ay += p2.y;
        ax += p3.x; ay += p3.y;
    }
    for (; e < end; e++) {
        float2 p = __half22float2(
            *reinterpret_cast<const __half2*>(in + (size_t)g_col[e] * 64 + off));
        ax += p.x; ay += p.y;
    }

    float dd = g_dinv[warp];
    ax *= dd; ay *= dd;
    if (bias) {
        const float2 b = *reinterpret_cast<const float2*>(bias + off);
        ax += b.x; ay += b.y;
    }
    if (ACT == 1) { ax = fmaxf(ax, 0.f); ay = fmaxf(ay, 0.f); }
    if (ACT == 2) {
        ax = 1.0f / (1.0f + expf(-ax));
        ay = 1.0f / (1.0f + expf(-ay));
    }
    if (PRESCALE) { ax *= dd; ay *= dd; }
    if (OUTH)
        *reinterpret_cast<__half2*>((__half*)out + (size_t)warp * 64 + off) =
            __floats2half2_rn(ax, ay);
    else
        *reinterpret_cast<float2*>((float*)out + (size_t)warp * 64 + off) =
            make_float2(ax, ay);
}

// in: fp16 [N][128]; OUTH: fp16 out, else fp32 out. Lane owns 4 halves (8B).
template <int ACT, int PRESCALE, int OUTH>
__global__ void __launch_bounds__(256) agg128h_kernel(
    const __half* __restrict__ in, void* __restrict__ out,
    const float* __restrict__ bias) {
    int warp = (blockIdx.x * blockDim.x + threadIdx.x) >> 5;
    if (warp >= N_NODES) return;
    int lane = threadIdx.x & 31;
    const int off = lane * 4;

    float ax, ay, az, aw;
    {
        uint2 u = *reinterpret_cast<const uint2*>(in + (size_t)warp * 128 + off);
        float2 f0 = __half22float2(*reinterpret_cast<__half2*>(&u.x));
        float2 f1 = __half22float2(*reinterpret_cast<__half2*>(&u.y));
        ax = f0.x; ay = f0.y; az = f1.x; aw = f1.y;
    }

    int e = g_rowbeg[warp], end = g_rowend[warp];
    for (; e + 4 <= end; e += 4) {
        int s0 = g_col[e], s1 = g_col[e+1], s2 = g_col[e+2], s3 = g_col[e+3];
        uint2 u0 = *reinterpret_cast<const uint2*>(in + (size_t)s0 * 128 + off);
        uint2 u1 = *reinterpret_cast<const uint2*>(in + (size_t)s1 * 128 + off);
        uint2 u2 = *reinterpret_cast<const uint2*>(in + (size_t)s2 * 128 + off);
        uint2 u3 = *reinterpret_cast<const uint2*>(in + (size_t)s3 * 128 + off);
        float2 a0 = __half22float2(*reinterpret_cast<__half2*>(&u0.x));
        float2 b0 = __half22float2(*reinterpret_cast<__half2*>(&u0.y));
        float2 a1 = __half22float2(*reinterpret_cast<__half2*>(&u1.x));
        float2 b1 = __half22float2(*reinterpret_cast<__half2*>(&u1.y));
        float2 a2 = __half22float2(*reinterpret_cast<__half2*>(&u2.x));
        float2 b2 = __half22float2(*reinterpret_cast<__half2*>(&u2.y));
        float2 a3 = __half22float2(*reinterpret_cast<__half2*>(&u3.x));
        float2 b3 = __half22float2(*reinterpret_cast<__half2*>(&u3.y));
        ax += a0.x; ay += a0.y; az += b0.x; aw += b0.y;
        ax += a1.x; ay += a1.y; az += b1.x; aw += b1.y;
        ax += a2.x; ay += a2.y; az += b2.x; aw += b2.y;
        ax += a3.x; ay += a3.y; az += b3.x; aw += b3.y;
    }
    for (; e < end; e++) {
        uint2 u = *reinterpret_cast<const uint2*>(in + (size_t)g_col[e] * 128 + off);
        float2 a = __half22float2(*reinterpret_cast<__half2*>(&u.x));
        float2 b = __half22float2(*reinterpret_cast<__half2*>(&u.y));
        ax += a.x; ay += a.y; az += b.x; aw += b.y;
    }

    float dd = g_dinv[warp];
    ax *= dd; ay *= dd; az *= dd; aw *= dd;
    if (bias) {
        const float4 b = *reinterpret_cast<const float4*>(bias + off);
        ax += b.x; ay += b.y; az += b.z; aw += b.w;
    }
    if (ACT == 1) {
        ax = fmaxf(ax, 0.f); ay = fmaxf(ay, 0.f);
        az = fmaxf(az, 0.f); aw = fmaxf(aw, 0.f);
    }
    if (PRESCALE) { ax *= dd; ay *= dd; az *= dd; aw *= dd; }
    if (OUTH) {
        uint2 u;
        u.x = h2_as_u32(__floats2half2_rn(ax, ay));
        u.y = h2_as_u32(__floats2half2_rn(az, aw));
        *reinterpret_cast<uint2*>((__half*)out + (size_t)warp * 128 + off) = u;
    } else {
        *reinterpret_cast<float4*>((float*)out + (size_t)warp * 128 + off) =
            make_float4(ax, ay, az, aw);
    }
}

// ---------------- launch ----------------
extern "C" void kernel_launch(void* const* d_in, const int* in_sizes, int n_in,
                              void* d_out, int out_size) {
    const float* x  = (const float*)d_in[0];
    const int*   ei = (const int*)d_in[1];   // int32! (JAX x64 disabled)
    const float* W1 = (const float*)d_in[2],  *b1 = (const float*)d_in[3];
    const float* W2 = (const float*)d_in[4],  *b2 = (const float*)d_in[5];
    const float* W3 = (const float*)d_in[6],  *b3 = (const float*)d_in[7];
    const float* W4 = (const float*)d_in[8],  *b4 = (const float*)d_in[9];
    const float* W5 = (const float*)d_in[10], *b5 = (const float*)d_in[11];
    const float* W6 = (const float*)d_in[12], *b6 = (const float*)d_in[13];
    float* out = (float*)d_out;

    float *bufA, *bufB;
    cudaGetSymbolAddress((void**)&bufA, g_bufA);
    cudaGetSymbolAddress((void**)&bufB, g_bufB);
    unsigned short *whi, *wlo;
    cudaGetSymbolAddress((void**)&whi, g_whi);
    cudaGetSymbolAddress((void**)&wlo, g_wlo);
    __half* hA = (__half*)bufA;
    __half* hB = (__half*)bufB;

    const int TB = 256;
    const int nodeBlocks = (N_NODES + TB - 1) / TB;
    const int edgeBlocks = (N_EDGES + TB - 1) / TB;
    const int aggBlocks  = (N_NODES * 32 + TB - 1) / TB;
    const int gemmRows   = (N_NODES + 127) / 128;

    const int wo1 = 0, wo2 = 8192, wo3 = 16384, wo4 = 49152, wo5 = 81920, wo6 = 90112;

    // opt-in dynamic smem for BN=128 variants (61.4 KB); idempotent, capture-safe
    cudaFuncSetAttribute(mma_gemm_kernel<128,1,1,1,0>,
                         cudaFuncAttributeMaxDynamicSharedMemorySize, MMA_SMEM(128));
    cudaFuncSetAttribute(mma_gemm_kernel<128,1,0,1,0>,
                         cudaFuncAttributeMaxDynamicSharedMemorySize, MMA_SMEM(128));
    cudaFuncSetAttribute(mma_gemm_kernel<128,0,1,1,0>,
                         cudaFuncAttributeMaxDynamicSharedMemorySize, MMA_SMEM(128));

    // ---- preprocessing: W split + counter zero (1 launch), then CSR ----
    wprep_zero_kernel<<<(W_TOTAL + TB - 1) / TB, TB>>>(W1, W2, W3, W4, W5, W6);
    hist_kernel<<<edgeBlocks, TB>>>(ei);
    alloc_kernel<<<nodeBlocks, TB>>>();
    scatter_kernel<<<edgeBlocks, TB>>>(ei);

    // L1: g1 = fp16( dinv .* (x@W1) )  [x rounded to fp16 in staging]
    mma_gemm_kernel<64,0,1,1,1><<<dim3(gemmRows, 1), TB, MMA_SMEM(64)>>>(
        x, whi + wo1, wlo + wo1, nullptr, hA, 128, 64);
    agg64h_kernel<1,1,1><<<aggBlocks, TB>>>(hA, hB, b1);   // <- profiled launch (#5)

    // L2: agg2 -> GEMM bias+relu+scale -> fp16 g2
    agg64h_kernel<0,0,1><<<aggBlocks, TB>>>(hB, hA, nullptr);
    mma_gemm_kernel<128,1,1,1,0><<<dim3(gemmRows, 1), TB, MMA_SMEM(128)>>>(
        hA, whi + wo2, wlo + wo2, b2, hB, 64, 128);

    // L3: agg3 -> GEMM bias+relu -> fp16 (L4 GEMM input)
    agg128h_kernel<0,0,1><<<aggBlocks, TB>>>(hB, hA, nullptr);
    mma_gemm_kernel<128,1,0,1,0><<<dim3(gemmRows, 2), TB, MMA_SMEM(128)>>>(
        hA, whi + wo3, wlo + wo3, b3, hB, 128, 256);

    // L4: GEMM scale -> fp16 g4; agg4 relu+b4 -> fp16
    mma_gemm_kernel<128,0,1,1,0><<<dim3(gemmRows, 1), TB, MMA_SMEM(128)>>>(
        hB, whi + wo4, wlo + wo4, nullptr, hA, 256, 128);
    agg128h_kernel<1,0,1><<<aggBlocks, TB>>>(hA, hB, b4);

    // L5: GEMM scale -> fp16 g5; agg5 relu+b5 -> fp16
    mma_gemm_kernel<64,0,1,1,0><<<dim3(gemmRows, 1), TB, MMA_SMEM(64)>>>(
        hB, whi + wo5, wlo + wo5, nullptr, hA, 128, 64);
    agg64h_kernel<1,0,1><<<aggBlocks, TB>>>(hA, hB, b5);

    // L6: GEMM scale -> fp16 g6; agg6 sigmoid+b6 -> fp32 d_out
    mma_gemm_kernel<64,0,1,1,0><<<dim3(gemmRows, 1), TB, MMA_SMEM(64)>>>(
        hB, whi + wo6, wlo + wo6, nullptr, hA, 64, 64);
    agg64h_kernel<2,0,0><<<aggBlocks, TB>>>(hA, out, b6);
}

// round 17
// speedup vs baseline: 1.2264x; 1.0002x over previous
#include <cuda_runtime.h>
#include <cuda_fp16.h>
#include <math.h>
#include <stdint.h>

#define N_NODES 50000
#define N_EDGES 800000
#define W_TOTAL 94208  // sum of K*Dout over 6 layers

// ---------------- static device scratch (allocation-free rule) ----------------
__device__ float g_bufA[N_NODES * 256];
__device__ float g_bufB[N_NODES * 256];
__device__ int   g_rowbeg[N_NODES];
__device__ int   g_rowend[N_NODES];
__device__ int   g_cursor[N_NODES];
__device__ int   g_cnt[N_NODES];
__device__ float g_dinv[N_NODES];
__device__ int   g_col[N_EDGES];
__device__ int   g_total;
__device__ unsigned short g_whi[W_TOTAL];  // fp16 hi, transposed [Dout][K]
__device__ unsigned short g_wlo[W_TOTAL];  // fp16 lo (residual)

__device__ __forceinline__ uint32_t h2_as_u32(__half2 h) {
    return *reinterpret_cast<uint32_t*>(&h);
}

// ---------------- W prep + counter zeroing (ONE launch, removes 2 memsets) ---------------
__global__ void wprep_zero_kernel(
    const float* __restrict__ W1, const float* __restrict__ W2,
    const float* __restrict__ W3, const float* __restrict__ W4,
    const float* __restrict__ W5, const float* __restrict__ W6) {
    int i = blockIdx.x * blockDim.x + threadIdx.x;
    if (i < N_NODES) g_cnt[i] = 0;
    if (i == 0) g_total = 0;
    if (i >= W_TOTAL) return;
    const float* W; int off, K, Dout;
    if      (i < 8192)  { W = W1; off = 0;     K = 128; Dout = 64;  }
    else if (i < 16384) { W = W2; off = 8192;  K = 64;  Dout = 128; }
    else if (i < 49152) { W = W3; off = 16384; K = 128; Dout = 256; }
    else if (i < 81920) { W = W4; off = 49152; K = 256; Dout = 128; }
    else if (i < 90112) { W = W5; off = 81920; K = 128; Dout = 64;  }
    else                { W = W6; off = 90112; K = 64;  Dout = 64;  }
    int local = i - off;
    int k = local / Dout, n = local % Dout;
    float v = W[local];
    __half h = __float2half_rn(v);
    float r = v - __half2float(h);
    g_whi[off + n * K + k] = __half_as_ushort(h);
    g_wlo[off + n * K + k] = __half_as_ushort(__float2half_rn(r));
}

// ---------------- CSR build (scan-free) ----------------
__global__ void hist_kernel(const int* __restrict__ ei) {
    int e = blockIdx.x * blockDim.x + threadIdx.x;
    if (e < N_EDGES) atomicAdd(&g_cnt[ei[N_EDGES + e]], 1);
}

__global__ void alloc_kernel() {
    int i = blockIdx.x * blockDim.x + threadIdx.x;
    if (i < N_NODES) {
        int c = g_cnt[i];
        g_dinv[i] = rsqrtf((float)c + 1.0f);
        int beg = atomicAdd(&g_total, c);
        g_rowbeg[i] = beg;
        g_rowend[i] = beg + c;
        g_cursor[i] = beg;
    }
}

__global__ void scatter_kernel(const int* __restrict__ ei) {
    int e = blockIdx.x * blockDim.x + threadIdx.x;
    if (e < N_EDGES) {
        int s = ei[e];
        int d = ei[N_EDGES + e];
        int pos = atomicAdd(&g_cursor[d], 1);
        g_col[pos] = s;
    }
}

// ---------------- warp MMA: m16n8k16 fp16 -> fp32 (sm_80+ PTX) ----------
__device__ __forceinline__ void mma16816(float* d, const uint32_t* a, const uint32_t* b) {
    asm volatile(
        "mma.sync.aligned.m16n8k16.row.col.f32.f16.f16.f32 "
        "{%0,%1,%2,%3}, {%4,%5,%6,%7}, {%8,%9}, {%0,%1,%2,%3};"
        : "+f"(d[0]), "+f"(d[1]), "+f"(d[2]), "+f"(d[3])
        : "r"(a[0]), "r"(a[1]), "r"(a[2]), "r"(a[3]), "r"(b[0]), "r"(b[1]));
}

// ---------------- tensor-core GEMM: C = A[NxK] @ W[KxDout] (fp16 A, W hi/lo, 2 MMAs) -----
// BM=128, BN in {64,128}, BK=32, 8 warps. Double-buffered smem with register prefetch:
// one __syncthreads per K-chunk; global loads of chunk c+1 overlap MMA of chunk c.
#define MMA_SMEM(BN) ((2 * 128 + 4 * (BN)) * 40 * 2)

template <int BN, int ACT, int SCALE, int HOUT, int AFP32>
__global__ void __launch_bounds__(256) mma_gemm_kernel(
    const void* __restrict__ Av,
    const unsigned short* __restrict__ whi, const unsigned short* __restrict__ wlo,
    const float* __restrict__ bias, void* __restrict__ Cv,
    int K, int Dout) {
    constexpr int BK = 32;
    constexpr int SA = 40;   // row stride in halves (80B)
    constexpr int NF = BN / 16;
    constexpr int ASZ = 128 * SA;
    constexpr int BSZ = BN * SA;
    extern __shared__ __align__(16) unsigned short sm[];
    unsigned short* Ah = sm;                 // [2][ASZ]
    unsigned short* Bh = sm + 2 * ASZ;       // [2][BSZ]
    unsigned short* Bl = Bh + 2 * BSZ;       // [2][BSZ]

    const int t = threadIdx.x;
    const int lane = t & 31, wid = t >> 5;
    const int g = lane >> 2, tc = lane & 3;
    const int warpRow = wid & 3, warpCol = wid >> 2;
    const int rowBase = blockIdx.x * 128;
    const int colBase = blockIdx.y * BN;

    // staging assignments: A rows (t>>2) and (t>>2)+64; B row (t>>2) (+64 if BN=128)
    const int sr = t >> 2;
    const int ac = (t & 3) * 8;

    auto loadA = [&](int row, int kb) {
        int grow = rowBase + row;
        uint4 packed = make_uint4(0, 0, 0, 0);
        if (grow < N_NODES) {
            if (AFP32) {
                const float* p = (const float*)Av + (size_t)grow * K + kb + ac;
                float4 x0 = *reinterpret_cast<const float4*>(p);
                float4 x1 = *reinterpret_cast<const float4*>(p + 4);
                packed.x = h2_as_u32(__floats2half2_rn(x0.x, x0.y));
                packed.y = h2_as_u32(__floats2half2_rn(x0.z, x0.w));
                packed.z = h2_as_u32(__floats2half2_rn(x1.x, x1.y));
                packed.w = h2_as_u32(__floats2half2_rn(x1.z, x1.w));
            } else {
                packed = *reinterpret_cast<const uint4*>(
                    (const __half*)Av + (size_t)grow * K + kb + ac);
            }
        }
        return packed;
    };

    float d[2][NF][4] = {};
    const int NCH = K / BK;

    // ---- prefetch + store chunk 0 ----
    uint4 a0 = loadA(sr, 0), a1 = loadA(sr + 64, 0);
    uint4 bh0, bl0, bh1, bl1;
    {
        size_t s0 = (size_t)(colBase + sr) * K + ac;
        bh0 = *reinterpret_cast<const uint4*>(whi + s0);
        bl0 = *reinterpret_cast<const uint4*>(wlo + s0);
        if (BN == 128) {
            size_t s1 = (size_t)(colBase + sr + 64) * K + ac;
            bh1 = *reinterpret_cast<const uint4*>(whi + s1);
            bl1 = *reinterpret_cast<const uint4*>(wlo + s1);
        }
    }
    *reinterpret_cast<uint4*>(&Ah[sr * SA + ac]) = a0;
    *reinterpret_cast<uint4*>(&Ah[(sr + 64) * SA + ac]) = a1;
    *reinterpret_cast<uint4*>(&Bh[sr * SA + ac]) = bh0;
    *reinterpret_cast<uint4*>(&Bl[sr * SA + ac]) = bl0;
    if (BN == 128) {
        *reinterpret_cast<uint4*>(&Bh[(sr + 64) * SA + ac]) = bh1;
        *reinterpret_cast<uint4*>(&Bl[(sr + 64) * SA + ac]) = bl1;
    }
    __syncthreads();

    for (int c = 0; c < NCH; c++) {
        const int cur = c & 1;
        const bool more = (c + 1 < NCH);
        if (more) {
            int kb = (c + 1) * BK;
            a0 = loadA(sr, kb);
            a1 = loadA(sr + 64, kb);
            size_t s0 = (size_t)(colBase + sr) * K + kb + ac;
            bh0 = *reinterpret_cast<const uint4*>(whi + s0);
            bl0 = *reinterpret_cast<const uint4*>(wlo + s0);
            if (BN == 128) {
                size_t s1 = (size_t)(colBase + sr + 64) * K + kb + ac;
                bh1 = *reinterpret_cast<const uint4*>(whi + s1);
                bl1 = *reinterpret_cast<const uint4*>(wlo + s1);
            }
        }
        const unsigned short* Ac  = Ah + cur * ASZ;
        const unsigned short* Bhc = Bh + cur * BSZ;
        const unsigned short* Blc = Bl + cur * BSZ;
        #pragma unroll
        for (int ks = 0; ks < 2; ks++) {
            const int kk = ks * 16;
            uint32_t ahf[2][4];
            #pragma unroll
            for (int i = 0; i < 2; i++) {
                int r0 = warpRow * 32 + i * 16 + g;
                uint2 x = *reinterpret_cast<const uint2*>(&Ac[r0 * SA + kk + tc * 4]);
                uint2 y = *reinterpret_cast<const uint2*>(&Ac[(r0 + 8) * SA + kk + tc * 4]);
                ahf[i][0] = x.x; ahf[i][2] = x.y; ahf[i][1] = y.x; ahf[i][3] = y.y;
            }
            #pragma unroll
            for (int j = 0; j < NF; j++) {
                int n = warpCol * (BN / 2) + j * 8 + g;
                uint32_t bhf[2], blf[2];
                uint2 x = *reinterpret_cast<const uint2*>(&Bhc[n * SA + kk + tc * 4]);
                bhf[0] = x.x; bhf[1] = x.y;
                uint2 y = *reinterpret_cast<const uint2*>(&Blc[n * SA + kk + tc * 4]);
                blf[0] = y.x; blf[1] = y.y;
                #pragma unroll
                for (int i = 0; i < 2; i++) {
                    mma16816(d[i][j], ahf[i], bhf);
                    mma16816(d[i][j], ahf[i], blf);
                }
            }
        }
        if (more) {
            const int nxt = cur ^ 1;
            *reinterpret_cast<uint4*>(&Ah[nxt * ASZ + sr * SA + ac]) = a0;
            *reinterpret_cast<uint4*>(&Ah[nxt * ASZ + (sr + 64) * SA + ac]) = a1;
            *reinterpret_cast<uint4*>(&Bh[nxt * BSZ + sr * SA + ac]) = bh0;
            *reinterpret_cast<uint4*>(&Bl[nxt * BSZ + sr * SA + ac]) = bl0;
            if (BN == 128) {
                *reinterpret_cast<uint4*>(&Bh[nxt * BSZ + (sr + 64) * SA + ac]) = bh1;
                *reinterpret_cast<uint4*>(&Bl[nxt * BSZ + (sr + 64) * SA + ac]) = bl1;
            }
        }
        __syncthreads();
    }

    // ---- epilogue ----
    #pragma unroll
    for (int i = 0; i < 2; i++) {
        int r0 = rowBase + warpRow * 32 + i * 16 + g;
        int r1 = r0 + 8;
        float s0 = 1.0f, s1 = 1.0f;
        if (SCALE) {
            if (r0 < N_NODES) s0 = g_dinv[r0];
            if (r1 < N_NODES) s1 = g_dinv[r1];
        }
        #pragma unroll
        for (int j = 0; j < NF; j++) {
            int col = colBase + warpCol * (BN / 2) + j * 8 + tc * 2;
            float b0 = 0.f, b1 = 0.f;
            if (bias) { b0 = bias[col]; b1 = bias[col + 1]; }
            float v0 = d[i][j][0] + b0, v1 = d[i][j][1] + b1;
            float v2 = d[i][j][2] + b0, v3 = d[i][j][3] + b1;
            if (ACT == 1) {
                v0 = fmaxf(v0, 0.f); v1 = fmaxf(v1, 0.f);
                v2 = fmaxf(v2, 0.f); v3 = fmaxf(v3, 0.f);
            }
            if (HOUT) {
                if (r0 < N_NODES)
                    *reinterpret_cast<__half2*>((__half*)Cv + (size_t)r0 * Dout + col) =
                        __floats2half2_rn(v0 * s0, v1 * s0);
                if (r1 < N_NODES)
                    *reinterpret_cast<__half2*>((__half*)Cv + (size_t)r1 * Dout + col) =
                        __floats2half2_rn(v2 * s1, v3 * s1);
            } else {
                if (r0 < N_NODES)
                    *reinterpret_cast<float2*>((float*)Cv + (size_t)r0 * Dout + col) =
                        make_float2(v0 * s0, v1 * s0);
                if (r1 < N_NODES)
                    *reinterpret_cast<float2*>((float*)Cv + (size_t)r1 * Dout + col) =
                        make_float2(v2 * s1, v3 * s1);
            }
        }
    }
}

// ---------------- Aggregation (separable norm, fp16 gather, fp32 accumulate) --------------
// in: fp16 [N][64]; OUTH: fp16 out, else fp32 out.
template <int ACT, int PRESCALE, int OUTH>  // ACT: 0 none, 1 relu, 2 sigmoid
__global__ void __launch_bounds__(256) agg64h_kernel(
    const __half* __restrict__ in, void* __restrict__ out,
    const float* __restrict__ bias) {
    int warp = (blockIdx.x * blockDim.x + threadIdx.x) >> 5;
    if (warp >= N_NODES) return;
    int lane = threadIdx.x & 31;
    const int off = lane * 2;

    float2 s = __half22float2(*reinterpret_cast<const __half2*>(in + (size_t)warp * 64 + off));
    float ax = s.x, ay = s.y;

    int e = g_rowbeg[warp], end = g_rowend[warp];
    for (; e + 4 <= end; e += 4) {
        int s0 = g_col[e], s1 = g_col[e+1], s2 = g_col[e+2], s3 = g_col[e+3];
        float2 p0 = __half22float2(*reinterpret_cast<const __half2*>(in + (size_t)s0 * 64 + off));
        float2 p1 = __half22float2(*reinterpret_cast<const __half2*>(in + (size_t)s1 * 64 + off));
        float2 p2 = __half22float2(*reinterpret_cast<const __half2*>(in + (size_t)s2 * 64 + off));
        float2 p3 = __half22float2(*reinterpret_cast<const __half2*>(in + (size_t)s3 * 64 + off));
        ax += p0.x; ay += p0.y;
        ax += p1.x; ay += p1.y;
        ax += p2.x; ay += p2.y;
        ax += p3.x; ay += p3.y;
    }
    for (; e < end; e++) {
        float2 p = __half22float2(
            *reinterpret_cast<const __half2*>(in + (size_t)g_col[e] * 64 + off));
        ax += p.x; ay += p.y;
    }

    float dd = g_dinv[warp];
    ax *= dd; ay *= dd;
    if (bias) {
        const float2 b = *reinterpret_cast<const float2*>(bias + off);
        ax += b.x; ay += b.y;
    }
    if (ACT == 1) { ax = fmaxf(ax, 0.f); ay = fmaxf(ay, 0.f); }
    if (ACT == 2) {
        ax = 1.0f / (1.0f + expf(-ax));
        ay = 1.0f / (1.0f + expf(-ay));
    }
    if (PRESCALE) { ax *= dd; ay *= dd; }
    if (OUTH)
        *reinterpret_cast<__half2*>((__half*)out + (size_t)warp * 64 + off) =
            __floats2half2_rn(ax, ay);
    else
        *reinterpret_cast<float2*>((float*)out + (size_t)warp * 64 + off) =
            make_float2(ax, ay);
}

// in: fp16 [N][128]; OUTH: fp16 out, else fp32 out. Lane owns 4 halves (8B).
template <int ACT, int PRESCALE, int OUTH>
__global__ void __launch_bounds__(256) agg128h_kernel(
    const __half* __restrict__ in, void* __restrict__ out,
    const float* __restrict__ bias) {
    int warp = (blockIdx.x * blockDim.x + threadIdx.x) >> 5;
    if (warp >= N_NODES) return;
    int lane = threadIdx.x & 31;
    const int off = lane * 4;

    float ax, ay, az, aw;
    {
        uint2 u = *reinterpret_cast<const uint2*>(in + (size_t)warp * 128 + off);
        float2 f0 = __half22float2(*reinterpret_cast<__half2*>(&u.x));
        float2 f1 = __half22float2(*reinterpret_cast<__half2*>(&u.y));
        ax = f0.x; ay = f0.y; az = f1.x; aw = f1.y;
    }

    int e = g_rowbeg[warp], end = g_rowend[warp];
    for (; e + 4 <= end; e += 4) {
        int s0 = g_col[e], s1 = g_col[e+1], s2 = g_col[e+2], s3 = g_col[e+3];
        uint2 u0 = *reinterpret_cast<const uint2*>(in + (size_t)s0 * 128 + off);
        uint2 u1 = *reinterpret_cast<const uint2*>(in + (size_t)s1 * 128 + off);
        uint2 u2 = *reinterpret_cast<const uint2*>(in + (size_t)s2 * 128 + off);
        uint2 u3 = *reinterpret_cast<const uint2*>(in + (size_t)s3 * 128 + off);
        float2 a0 = __half22float2(*reinterpret_cast<__half2*>(&u0.x));
        float2 b0 = __half22float2(*reinterpret_cast<__half2*>(&u0.y));
        float2 a1 = __half22float2(*reinterpret_cast<__half2*>(&u1.x));
        float2 b1 = __half22float2(*reinterpret_cast<__half2*>(&u1.y));
        float2 a2 = __half22float2(*reinterpret_cast<__half2*>(&u2.x));
        float2 b2 = __half22float2(*reinterpret_cast<__half2*>(&u2.y));
        float2 a3 = __half22float2(*reinterpret_cast<__half2*>(&u3.x));
        float2 b3 = __half22float2(*reinterpret_cast<__half2*>(&u3.y));
        ax += a0.x; ay += a0.y; az += b0.x; aw += b0.y;
        ax += a1.x; ay += a1.y; az += b1.x; aw += b1.y;
        ax += a2.x; ay += a2.y; az += b2.x; aw += b2.y;
        ax += a3.x; ay += a3.y; az += b3.x; aw += b3.y;
    }
    for (; e < end; e++) {
        uint2 u = *reinterpret_cast<const uint2*>(in + (size_t)g_col[e] * 128 + off);
        float2 a = __half22float2(*reinterpret_cast<__half2*>(&u.x));
        float2 b = __half22float2(*reinterpret_cast<__half2*>(&u.y));
        ax += a.x; ay += a.y; az += b.x; aw += b.y;
    }

    float dd = g_dinv[warp];
    ax *= dd; ay *= dd; az *= dd; aw *= dd;
    if (bias) {
        const float4 b = *reinterpret_cast<const float4*>(bias + off);
        ax += b.x; ay += b.y; az += b.z; aw += b.w;
    }
    if (ACT == 1) {
        ax = fmaxf(ax, 0.f); ay = fmaxf(ay, 0.f);
        az = fmaxf(az, 0.f); aw = fmaxf(aw, 0.f);
    }
    if (PRESCALE) { ax *= dd; ay *= dd; az *= dd; aw *= dd; }
    if (OUTH) {
        uint2 u;
        u.x = h2_as_u32(__floats2half2_rn(ax, ay));
        u.y = h2_as_u32(__floats2half2_rn(az, aw));
        *reinterpret_cast<uint2*>((__half*)out + (size_t)warp * 128 + off) = u;
    } else {
        *reinterpret_cast<float4*>((float*)out + (size_t)warp * 128 + off) =
            make_float4(ax, ay, az, aw);
    }
}

// ---------------- launch ----------------
extern "C" void kernel_launch(void* const* d_in, const int* in_sizes, int n_in,
                              void* d_out, int out_size) {
    const float* x  = (const float*)d_in[0];
    const int*   ei = (const int*)d_in[1];   // int32! (JAX x64 disabled)
    const float* W1 = (const float*)d_in[2],  *b1 = (const float*)d_in[3];
    const float* W2 = (const float*)d_in[4],  *b2 = (const float*)d_in[5];
    const float* W3 = (const float*)d_in[6],  *b3 = (const float*)d_in[7];
    const float* W4 = (const float*)d_in[8],  *b4 = (const float*)d_in[9];
    const float* W5 = (const float*)d_in[10], *b5 = (const float*)d_in[11];
    const float* W6 = (const float*)d_in[12], *b6 = (const float*)d_in[13];
    float* out = (float*)d_out;

    float *bufA, *bufB;
    cudaGetSymbolAddress((void**)&bufA, g_bufA);
    cudaGetSymbolAddress((void**)&bufB, g_bufB);
    unsigned short *whi, *wlo;
    cudaGetSymbolAddress((void**)&whi, g_whi);
    cudaGetSymbolAddress((void**)&wlo, g_wlo);
    __half* hA = (__half*)bufA;
    __half* hB = (__half*)bufB;

    const int TB = 256;
    const int nodeBlocks = (N_NODES + TB - 1) / TB;
    const int edgeBlocks = (N_EDGES + TB - 1) / TB;
    const int aggBlocks  = (N_NODES * 32 + TB - 1) / TB;
    const int gemmRows   = (N_NODES + 127) / 128;

    const int wo1 = 0, wo2 = 8192, wo3 = 16384, wo4 = 49152, wo5 = 81920, wo6 = 90112;

    // opt-in dynamic smem for BN=128 variants (61.4 KB); idempotent, capture-safe
    cudaFuncSetAttribute(mma_gemm_kernel<128,1,1,1,0>,
                         cudaFuncAttributeMaxDynamicSharedMemorySize, MMA_SMEM(128));
    cudaFuncSetAttribute(mma_gemm_kernel<128,1,0,1,0>,
                         cudaFuncAttributeMaxDynamicSharedMemorySize, MMA_SMEM(128));
    cudaFuncSetAttribute(mma_gemm_kernel<128,0,1,1,0>,
                         cudaFuncAttributeMaxDynamicSharedMemorySize, MMA_SMEM(128));

    // ---- preprocessing: W split + counter zero (1 launch), then CSR ----
    wprep_zero_kernel<<<(W_TOTAL + TB - 1) / TB, TB>>>(W1, W2, W3, W4, W5, W6);
    hist_kernel<<<edgeBlocks, TB>>>(ei);
    alloc_kernel<<<nodeBlocks, TB>>>();
    scatter_kernel<<<edgeBlocks, TB>>>(ei);

    // L1: g1 = fp16( dinv .* (x@W1) )  [x rounded to fp16 in staging]
    mma_gemm_kernel<64,0,1,1,1><<<dim3(gemmRows, 1), TB, MMA_SMEM(64)>>>(
        x, whi + wo1, wlo + wo1, nullptr, hA, 128, 64);
    agg64h_kernel<1,1,1><<<aggBlocks, TB>>>(hA, hB, b1);   // <- profiled launch (#5)

    // L2: agg2 -> GEMM bias+relu+scale -> fp16 g2
    agg64h_kernel<0,0,1><<<aggBlocks, TB>>>(hB, hA, nullptr);
    mma_gemm_kernel<128,1,1,1,0><<<dim3(gemmRows, 1), TB, MMA_SMEM(128)>>>(
        hA, whi + wo2, wlo + wo2, b2, hB, 64, 128);

    // L3: agg3 -> GEMM bias+relu -> fp16 (L4 GEMM input)
    agg128h_kernel<0,0,1><<<aggBlocks, TB>>>(hB, hA, nullptr);
    mma_gemm_kernel<128,1,0,1,0><<<dim3(gemmRows, 2), TB, MMA_SMEM(128)>>>(
        hA, whi + wo3, wlo + wo3, b3, hB, 128, 256);

    // L4: GEMM scale -> fp16 g4; agg4 relu+b4 -> fp16
    mma_gemm_kernel<128,0,1,1,0><<<dim3(gemmRows, 1), TB, MMA_SMEM(128)>>>(
        hB, whi + wo4, wlo + wo4, nullptr, hA, 256, 128);
    agg128h_kernel<1,0,1><<<aggBlocks, TB>>>(hA, hB, b4);

    // L5: GEMM scale -> fp16 g5; agg5 relu+b5 -> fp16
    mma_gemm_kernel<64,0,1,1,0><<<dim3(gemmRows, 1), TB, MMA_SMEM(64)>>>(
        hB, whi + wo5, wlo + wo5, nullptr, hA, 128, 64);
    agg64h_kernel<1,0,1><<<aggBlocks, TB>>>(hA, hB, b5);

    // L6: GEMM scale -> fp16 g6; agg6 sigmoid+b6 -> fp32 d_out
    mma_gemm_kernel<64,0,1,1,0><<<dim3(gemmRows, 1), TB, MMA_SMEM(64)>>>(
        hB, whi + wo6, wlo + wo6, nullptr, hA, 64, 64);
    agg64h_kernel<2,0,0><<<aggBlocks, TB>>>(hA, out, b6);
}